// round 8
// baseline (speedup 1.0000x reference)
#include <cuda_runtime.h>
#include <cuda_fp16.h>
#include <mma.h>
#include <cstdint>
#include <cstddef>

using namespace nvcuda;

#define N_NODES  100000
#define N_PAD    100096   // padded to multiple of 128 for GEMM A-tile reads
#define N_EDGES  1600000
#define DIM      128
#define N_GRAPHS 512

// ---------------- scratch (static device globals; no allocation) ----------------
__device__ __align__(16) __half g_x16[(size_t)N_PAD * DIM];     // fp16 copy of x
__device__ __align__(16) __half g_h16[(size_t)N_NODES * DIM];   // GEMM output (gather src)
__device__ __align__(16) __half g_h16b[(size_t)N_PAD * DIM];    // agg out fp16 (GEMM2 A / layer3 src)
__device__ __align__(16) float  g_agg[(size_t)N_NODES * DIM];   // fp32 aggregated (readout src)
__device__ __align__(16) __half g_w16[2][DIM * DIM];            // fp16 W1, W2 (row-major [k][n])
__device__ __align__(16) float  g_dinv[N_NODES];
__device__ __align__(16) int    g_cnt[N_NODES];
__device__ __align__(16) int    g_off[N_NODES];
__device__ __align__(16) int    g_cur[N_NODES];
__device__ __align__(16) int2   g_csr[N_EDGES];                 // {src, w as bits}
__device__ __align__(16) float  g_gsum[N_GRAPHS * DIM];
__device__ __align__(16) float  g_gcnt[N_GRAPHS];
__device__ int g_partial[32];

// ---------------- setup kernels ----------------
__global__ void k_zero() {
    int i = blockIdx.x * blockDim.x + threadIdx.x;
    if (i < N_NODES) g_cnt[i] = 0;
    if (i < N_GRAPHS * DIM) g_gsum[i] = 0.f;
    if (i < N_GRAPHS) g_gcnt[i] = 0.f;
}

__global__ void k_degree(const int* __restrict__ ei) {
    int e4 = (blockIdx.x * blockDim.x + threadIdx.x) * 4;
    if (e4 + 3 < N_EDGES) {
        int4 d = *(const int4*)(ei + N_EDGES + e4);
        if ((unsigned)d.x < N_NODES) atomicAdd(&g_cnt[d.x], 1);
        if ((unsigned)d.y < N_NODES) atomicAdd(&g_cnt[d.y], 1);
        if ((unsigned)d.z < N_NODES) atomicAdd(&g_cnt[d.z], 1);
        if ((unsigned)d.w < N_NODES) atomicAdd(&g_cnt[d.w], 1);
    }
}

// x fp32 -> fp16 (8 elems/thread)
__global__ void k_prepx(const float* __restrict__ x) {
    size_t i = ((size_t)blockIdx.x * blockDim.x + threadIdx.x) * 8;
    if (i < (size_t)N_NODES * DIM) {
        float4 v0 = *(const float4*)(x + i);
        float4 v1 = *(const float4*)(x + i + 4);
        __half2 h0 = __floats2half2_rn(v0.x, v0.y);
        __half2 h1 = __floats2half2_rn(v0.z, v0.w);
        __half2 h2 = __floats2half2_rn(v1.x, v1.y);
        __half2 h3 = __floats2half2_rn(v1.z, v1.w);
        uint4 o;
        o.x = *(unsigned*)&h0; o.y = *(unsigned*)&h1;
        o.z = *(unsigned*)&h2; o.w = *(unsigned*)&h3;
        *(uint4*)(g_x16 + i) = o;
    }
}

// W1/W2 fp32 -> fp16 row-major (blockIdx selects which)
__global__ __launch_bounds__(256) void k_prepw(const float* __restrict__ Wa,
                                               const float* __restrict__ Wb) {
    const float* W = blockIdx.x ? Wb : Wa;
    __half* o = g_w16[blockIdx.x];
    for (int i = threadIdx.x * 8; i < DIM * DIM; i += 256 * 8) {
        float4 v0 = *(const float4*)(W + i);
        float4 v1 = *(const float4*)(W + i + 4);
        __half2 h0 = __floats2half2_rn(v0.x, v0.y);
        __half2 h1 = __floats2half2_rn(v0.z, v0.w);
        __half2 h2 = __floats2half2_rn(v1.x, v1.y);
        __half2 h3 = __floats2half2_rn(v1.z, v1.w);
        uint4 ov;
        ov.x = *(unsigned*)&h0; ov.y = *(unsigned*)&h1;
        ov.z = *(unsigned*)&h2; ov.w = *(unsigned*)&h3;
        *(uint4*)(o + i) = ov;
    }
}

__global__ __launch_bounds__(1024) void k_scan1() {
    __shared__ int warp_sums[32];
    int t = threadIdx.x, lane = t & 31, wid = t >> 5;
    int i0 = blockIdx.x * 4096 + t * 4;
    int v[4];
#pragma unroll
    for (int q = 0; q < 4; q++) {
        int i = i0 + q;
        v[q] = (i < N_NODES) ? g_cnt[i] : 0;
        if (i < N_NODES) g_dinv[i] = rsqrtf((float)v[q] + 1.0f);
    }
    int tsum = v[0] + v[1] + v[2] + v[3];
    int x = tsum;
#pragma unroll
    for (int s = 1; s < 32; s <<= 1) {
        int y = __shfl_up_sync(0xffffffffu, x, s);
        if (lane >= s) x += y;
    }
    if (lane == 31) warp_sums[wid] = x;
    __syncthreads();
    if (wid == 0) {
        int ws = warp_sums[lane];
        int xx = ws;
#pragma unroll
        for (int s = 1; s < 32; s <<= 1) {
            int y = __shfl_up_sync(0xffffffffu, xx, s);
            if (lane >= s) xx += y;
        }
        warp_sums[lane] = xx - ws;
    }
    __syncthreads();
    int run = warp_sums[wid] + (x - tsum);
#pragma unroll
    for (int q = 0; q < 4; q++) {
        int i = i0 + q;
        if (i < N_NODES) g_off[i] = run;
        run += v[q];
    }
    if (t == 1023) g_partial[blockIdx.x] = warp_sums[31] + x;
}

__global__ void k_scan3(int nblk) {
    __shared__ int sp[32];
    int t = threadIdx.x;
    if (t < 32) {
        int v = (t < nblk) ? g_partial[t] : 0;
        int x = v;
#pragma unroll
        for (int s = 1; s < 32; s <<= 1) {
            int y = __shfl_up_sync(0xffffffffu, x, s);
            if ((t & 31) >= s) x += y;
        }
        sp[t] = x - v;
    }
    __syncthreads();
    int i = blockIdx.x * blockDim.x + t;
    if (i < N_NODES) {
        int o = g_off[i] + sp[i >> 12];
        g_off[i] = o;
        g_cur[i] = o;
    }
}

__global__ void k_fill(const int* __restrict__ ei) {
    int e4 = (blockIdx.x * blockDim.x + threadIdx.x) * 4;
    if (e4 + 3 < N_EDGES) {
        int4 s = *(const int4*)(ei + e4);
        int4 d = *(const int4*)(ei + N_EDGES + e4);
        int ss[4] = {s.x, s.y, s.z, s.w};
        int dd[4] = {d.x, d.y, d.z, d.w};
#pragma unroll
        for (int q = 0; q < 4; q++) {
            if ((unsigned)ss[q] < N_NODES && (unsigned)dd[q] < N_NODES) {
                int pos = atomicAdd(&g_cur[dd[q]], 1);
                if ((unsigned)pos < N_EDGES) {
                    float w = g_dinv[ss[q]] * g_dinv[dd[q]];
                    g_csr[pos] = make_int2(ss[q], __float_as_int(w));
                }
            }
        }
    }
}

// ---------------- wmma GEMM: g_h16 = fp16( A(fp16) @ W16[widx] ) ----------------
// 256 threads = 8 warps; each warp does 16 rows x 128 cols. A read from global fp16.
__global__ __launch_bounds__(256, 2) void k_gemm_w(int a_sel, int widx) {
    __shared__ __align__(16) __half Ws[DIM * DIM];  // 32 KB
    const __half* A = a_sel ? g_h16b : g_x16;
    int tid = threadIdx.x;
    int wid = tid >> 5, lane = tid & 31;

    // load W tile (2048 uint4 by 256 threads)
    {
        const uint4* src = (const uint4*)g_w16[widx];
        uint4* dst = (uint4*)Ws;
#pragma unroll
        for (int i = 0; i < 8; i++) dst[tid + i * 256] = src[tid + i * 256];
    }
    __syncthreads();

    int r0 = blockIdx.x * 128 + wid * 16;
    wmma::fragment<wmma::accumulator, 16, 16, 16, float> acc[8];
#pragma unroll
    for (int n = 0; n < 8; n++) wmma::fill_fragment(acc[n], 0.f);

    const __half* Arow = A + (size_t)r0 * DIM;
#pragma unroll
    for (int k = 0; k < 8; k++) {
        wmma::fragment<wmma::matrix_a, 16, 16, 16, __half, wmma::row_major> af;
        wmma::load_matrix_sync(af, Arow + k * 16, DIM);
#pragma unroll
        for (int n = 0; n < 8; n++) {
            wmma::fragment<wmma::matrix_b, 16, 16, 16, __half, wmma::row_major> bf;
            wmma::load_matrix_sync(bf, Ws + k * 16 * DIM + n * 16, DIM);
            wmma::mma_sync(acc[n], af, bf, acc[n]);
        }
    }
    __syncthreads();  // done reading Ws; reuse as per-warp C staging

    float* Cs = (float*)Ws + wid * 1024;  // 16 x 64 f32 per warp (4 KB)
#pragma unroll
    for (int h = 0; h < 2; h++) {
#pragma unroll
        for (int n = 0; n < 4; n++)
            wmma::store_matrix_sync(Cs + n * 16, acc[h * 4 + n], 64, wmma::mem_row_major);
        __syncwarp();
        int r = lane >> 1;              // 0..15
        int cb = (lane & 1) * 32;       // 0 or 32
        int grow = r0 + r;
        if (grow < N_NODES) {
            const float* srcr = Cs + r * 64 + cb;
            __half* dstp = g_h16 + (size_t)grow * DIM + h * 64 + cb;
#pragma unroll
            for (int j = 0; j < 32; j += 8) {
                float4 v0 = *(const float4*)(srcr + j);
                float4 v1 = *(const float4*)(srcr + j + 4);
                __half2 h0 = __floats2half2_rn(v0.x, v0.y);
                __half2 h1 = __floats2half2_rn(v0.z, v0.w);
                __half2 h2 = __floats2half2_rn(v1.x, v1.y);
                __half2 h3 = __floats2half2_rn(v1.z, v1.w);
                uint4 o;
                o.x = *(unsigned*)&h0; o.y = *(unsigned*)&h1;
                o.z = *(unsigned*)&h2; o.w = *(unsigned*)&h3;
                *(uint4*)(dstp + j) = o;
            }
        }
        __syncwarp();
    }
}

// ---------------- edge aggregation (fp16 gather): one warp per dest node ----------
// in_sel: 0 = g_h16, 1 = g_h16b.  out_f16: 0 -> g_agg (fp32), 1 -> g_h16b (fp16).
__global__ __launch_bounds__(256) void k_agg(int in_sel, int out_f16,
                                             const float* __restrict__ bias) {
    int n = (blockIdx.x * blockDim.x + threadIdx.x) >> 5;
    int lane = threadIdx.x & 31;
    if (n >= N_NODES) return;
    const uint2* in2 = (const uint2*)(in_sel ? g_h16b : g_h16);
    float dn = g_dinv[n];
    float sw = dn * dn;
    uint2 sv = in2[(size_t)n * 32 + lane];
    float2 sf0 = __half22float2(*(__half2*)&sv.x), sf1 = __half22float2(*(__half2*)&sv.y);
    float4 acc;
    acc.x = sw * sf0.x; acc.y = sw * sf0.y; acc.z = sw * sf1.x; acc.w = sw * sf1.y;
    int j = g_off[n];
    int end = j + g_cnt[n];
    for (; j + 4 <= end; j += 4) {
        int2 e0 = g_csr[j], e1 = g_csr[j + 1], e2 = g_csr[j + 2], e3 = g_csr[j + 3];
        float w0 = __int_as_float(e0.y), w1 = __int_as_float(e1.y);
        float w2 = __int_as_float(e2.y), w3 = __int_as_float(e3.y);
        uint2 r0 = in2[(size_t)e0.x * 32 + lane];
        uint2 r1 = in2[(size_t)e1.x * 32 + lane];
        uint2 r2 = in2[(size_t)e2.x * 32 + lane];
        uint2 r3 = in2[(size_t)e3.x * 32 + lane];
        float2 f0a = __half22float2(*(__half2*)&r0.x), f0b = __half22float2(*(__half2*)&r0.y);
        float2 f1a = __half22float2(*(__half2*)&r1.x), f1b = __half22float2(*(__half2*)&r1.y);
        float2 f2a = __half22float2(*(__half2*)&r2.x), f2b = __half22float2(*(__half2*)&r2.y);
        float2 f3a = __half22float2(*(__half2*)&r3.x), f3b = __half22float2(*(__half2*)&r3.y);
        acc.x += w0 * f0a.x; acc.y += w0 * f0a.y; acc.z += w0 * f0b.x; acc.w += w0 * f0b.y;
        acc.x += w1 * f1a.x; acc.y += w1 * f1a.y; acc.z += w1 * f1b.x; acc.w += w1 * f1b.y;
        acc.x += w2 * f2a.x; acc.y += w2 * f2a.y; acc.z += w2 * f2b.x; acc.w += w2 * f2b.y;
        acc.x += w3 * f3a.x; acc.y += w3 * f3a.y; acc.z += w3 * f3b.x; acc.w += w3 * f3b.y;
    }
    for (; j < end; j++) {
        int2 e = g_csr[j];
        float w = __int_as_float(e.y);
        uint2 r = in2[(size_t)e.x * 32 + lane];
        float2 fa = __half22float2(*(__half2*)&r.x), fb = __half22float2(*(__half2*)&r.y);
        acc.x += w * fa.x; acc.y += w * fa.y; acc.z += w * fb.x; acc.w += w * fb.y;
    }
    if (bias) {
        const float4 b = *(const float4*)(bias + lane * 4);
        acc.x = fmaxf(acc.x + b.x, 0.f);
        acc.y = fmaxf(acc.y + b.y, 0.f);
        acc.z = fmaxf(acc.z + b.z, 0.f);
        acc.w = fmaxf(acc.w + b.w, 0.f);
    }
    if (out_f16) {
        __half2 o0 = __floats2half2_rn(acc.x, acc.y);
        __half2 o1 = __floats2half2_rn(acc.z, acc.w);
        uint2 ov;
        ov.x = *(unsigned*)&o0; ov.y = *(unsigned*)&o1;
        ((uint2*)g_h16b)[(size_t)n * 32 + lane] = ov;
    } else {
        ((float4*)g_agg)[(size_t)n * 32 + lane] = acc;
    }
}

// ---------------- readout: segmented sum of g_agg over sorted batch ids ----------
#define NPB 256
__global__ void k_readout(const int* __restrict__ batch) {
    int d = threadIdx.x;
    int n0 = blockIdx.x * NPB;
    if (n0 >= N_NODES) return;
    int n1 = n0 + NPB;
    if (n1 > N_NODES) n1 = N_NODES;
    int curb = batch[n0];
    if ((unsigned)curb >= N_GRAPHS) curb = 0;
    float acc = 0.f;
    int c = 0;
    for (int n = n0; n < n1; n++) {
        int b = batch[n];
        if ((unsigned)b >= N_GRAPHS) b = 0;
        if (b != curb) {
            atomicAdd(&g_gsum[curb * DIM + d], acc);
            if (d == 0) atomicAdd(&g_gcnt[curb], (float)c);
            acc = 0.f; c = 0; curb = b;
        }
        acc += g_agg[(size_t)n * DIM + d];
        c++;
    }
    atomicAdd(&g_gsum[curb * DIM + d], acc);
    if (d == 0) atomicAdd(&g_gcnt[curb], (float)c);
}

// ---------------- final: out[g] = mean_vec(g) @ W3 + b3 (0 if empty graph) --------
__global__ __launch_bounds__(128) void k_final(const float* __restrict__ W3,
                                               const float* __restrict__ b3,
                                               float* __restrict__ out) {
    __shared__ float m[DIM];
    int g = blockIdx.x;
    int d = threadIdx.x;
    float c = g_gcnt[g];
    float inv = (c > 0.f) ? (1.f / c) : 0.f;
    m[d] = g_gsum[g * DIM + d] * inv;
    __syncthreads();
    float acc = 0.f;
#pragma unroll 8
    for (int k = 0; k < DIM; k++)
        acc = fmaf(m[k], W3[k * DIM + d], acc);
    out[g * DIM + d] = (c > 0.f) ? (acc + b3[d]) : 0.f;
}

// ---------------- launch ----------------
extern "C" void kernel_launch(void* const* d_in, const int* in_sizes, int n_in,
                              void* d_out, int out_size) {
    (void)in_sizes; (void)n_in; (void)out_size;
    const float* x     = (const float*)d_in[0];
    const int*   ei    = (const int*)d_in[1];
    const int*   batch = (const int*)d_in[2];
    const float* W1    = (const float*)d_in[3];
    const float* b1    = (const float*)d_in[4];
    const float* W2    = (const float*)d_in[5];
    const float* b2    = (const float*)d_in[6];
    const float* W3    = (const float*)d_in[7];
    const float* b3    = (const float*)d_in[8];
    float* out = (float*)d_out;

    int scan_blocks = (N_NODES + 4095) / 4096;

    k_zero<<<(N_NODES + 255) / 256, 256>>>();
    k_degree<<<(N_EDGES / 4 + 255) / 256, 256>>>(ei);
    k_prepx<<<(int)(((size_t)N_NODES * DIM / 8 + 255) / 256), 256>>>(x);
    k_prepw<<<2, 256>>>(W1, W2);
    k_scan1<<<scan_blocks, 1024>>>();
    k_scan3<<<(N_NODES + 255) / 256, 256>>>(scan_blocks);
    k_fill<<<(N_EDGES / 4 + 255) / 256, 256>>>(ei);

    int gemm_blocks = (N_NODES + 127) / 128;  // 782
    int agg_blocks = (N_NODES * 32 + 255) / 256;

    // layer 1: h16 = fp16(x16 @ W1) ; agg -> g_h16b fp16 with fused relu(.+b1)
    k_gemm_w<<<gemm_blocks, 256>>>(0, 0);
    k_agg<<<agg_blocks, 256>>>(0, 1, b1);
    // layer 2: h16 = fp16(h16b @ W2) ; agg -> g_h16b fp16 with fused relu(.+b2)
    k_gemm_w<<<gemm_blocks, 256>>>(1, 1);
    k_agg<<<agg_blocks, 256>>>(0, 1, b2);
    // layer 3: agg(g_h16b) -> g_agg (fp32) ; W3 applied post-pooling
    k_agg<<<agg_blocks, 256>>>(1, 0, nullptr);

    k_readout<<<(N_NODES + NPB - 1) / NPB, 128>>>(batch);
    k_final<<<N_GRAPHS, 128>>>(W3, b3, out);
}

// round 9
// speedup vs baseline: 1.2380x; 1.2380x over previous
#include <cuda_runtime.h>
#include <cuda_fp16.h>
#include <mma.h>
#include <cstdint>
#include <cstddef>

using namespace nvcuda;

#define N_NODES  100000
#define N_PAD    100096   // multiple of 128
#define N_EDGES  1600000
#define DIM      128
#define N_GRAPHS 512

// ---------------- scratch ----------------
__device__ __align__(16) __half g_h16[(size_t)N_NODES * DIM];   // GEMM out (gather src)
__device__ __align__(16) __half g_h16b[(size_t)N_PAD * DIM];    // agg out fp16 (GEMM A / layer3 src)
__device__ __align__(16) float  g_agg[(size_t)N_NODES * DIM];   // fp32 aggregated (readout src)
__device__ __align__(16) __half g_w16[2][DIM * DIM];            // fp16 W1, W2 row-major
__device__ __align__(16) float  g_dinv[N_NODES];
__device__ __align__(16) int    g_cnt[N_NODES];
__device__ __align__(16) int    g_off[N_NODES];
__device__ __align__(16) int    g_cur[N_NODES];
__device__ __align__(16) int2   g_csr[N_EDGES];
__device__ __align__(16) float  g_gsum[N_GRAPHS * DIM];
__device__ __align__(16) float  g_gcnt[N_GRAPHS];
__device__ int g_partial[32];

// ---------------- setup ----------------
__global__ void k_zero() {
    int i = blockIdx.x * blockDim.x + threadIdx.x;
    if (i < N_NODES) g_cnt[i] = 0;
    if (i < N_GRAPHS * DIM) g_gsum[i] = 0.f;
    if (i < N_GRAPHS) g_gcnt[i] = 0.f;
}

// 16 blocks: bit3 selects W, bits0-2 select 2048-elem chunk
__global__ __launch_bounds__(256) void k_prepw(const float* __restrict__ Wa,
                                               const float* __restrict__ Wb) {
    int w = blockIdx.x >> 3;
    const float* W = w ? Wb : Wa;
    __half* o = g_w16[w];
    int i = (blockIdx.x & 7) * 2048 + threadIdx.x * 8;
    float4 v0 = *(const float4*)(W + i);
    float4 v1 = *(const float4*)(W + i + 4);
    __half2 h0 = __floats2half2_rn(v0.x, v0.y);
    __half2 h1 = __floats2half2_rn(v0.z, v0.w);
    __half2 h2 = __floats2half2_rn(v1.x, v1.y);
    __half2 h3 = __floats2half2_rn(v1.z, v1.w);
    uint4 ov;
    ov.x = *(unsigned*)&h0; ov.y = *(unsigned*)&h1;
    ov.z = *(unsigned*)&h2; ov.w = *(unsigned*)&h3;
    *(uint4*)(o + i) = ov;
}

__global__ void k_degree(const int* __restrict__ ei) {
    int e4 = (blockIdx.x * blockDim.x + threadIdx.x) * 4;
    if (e4 + 3 < N_EDGES) {
        int4 d = *(const int4*)(ei + N_EDGES + e4);
        if ((unsigned)d.x < N_NODES) atomicAdd(&g_cnt[d.x], 1);
        if ((unsigned)d.y < N_NODES) atomicAdd(&g_cnt[d.y], 1);
        if ((unsigned)d.z < N_NODES) atomicAdd(&g_cnt[d.z], 1);
        if ((unsigned)d.w < N_NODES) atomicAdd(&g_cnt[d.w], 1);
    }
}

__global__ __launch_bounds__(1024) void k_scan1() {
    __shared__ int warp_sums[32];
    int t = threadIdx.x, lane = t & 31, wid = t >> 5;
    int i0 = blockIdx.x * 4096 + t * 4;
    int v[4];
#pragma unroll
    for (int q = 0; q < 4; q++) {
        int i = i0 + q;
        v[q] = (i < N_NODES) ? g_cnt[i] : 0;
        if (i < N_NODES) g_dinv[i] = rsqrtf((float)v[q] + 1.0f);
    }
    int tsum = v[0] + v[1] + v[2] + v[3];
    int x = tsum;
#pragma unroll
    for (int s = 1; s < 32; s <<= 1) {
        int y = __shfl_up_sync(0xffffffffu, x, s);
        if (lane >= s) x += y;
    }
    if (lane == 31) warp_sums[wid] = x;
    __syncthreads();
    if (wid == 0) {
        int ws = warp_sums[lane];
        int xx = ws;
#pragma unroll
        for (int s = 1; s < 32; s <<= 1) {
            int y = __shfl_up_sync(0xffffffffu, xx, s);
            if (lane >= s) xx += y;
        }
        warp_sums[lane] = xx - ws;
    }
    __syncthreads();
    int run = warp_sums[wid] + (x - tsum);
#pragma unroll
    for (int q = 0; q < 4; q++) {
        int i = i0 + q;
        if (i < N_NODES) g_off[i] = run;
        run += v[q];
    }
    if (t == 1023) g_partial[blockIdx.x] = warp_sums[31] + x;
}

__global__ void k_scan3(int nblk) {
    __shared__ int sp[32];
    int t = threadIdx.x;
    if (t < 32) {
        int v = (t < nblk) ? g_partial[t] : 0;
        int x = v;
#pragma unroll
        for (int s = 1; s < 32; s <<= 1) {
            int y = __shfl_up_sync(0xffffffffu, x, s);
            if ((t & 31) >= s) x += y;
        }
        sp[t] = x - v;
    }
    __syncthreads();
    int i = blockIdx.x * blockDim.x + t;
    if (i < N_NODES) {
        int o = g_off[i] + sp[i >> 12];
        g_off[i] = o;
        g_cur[i] = o;
    }
}

__global__ void k_fill(const int* __restrict__ ei) {
    int e4 = (blockIdx.x * blockDim.x + threadIdx.x) * 4;
    if (e4 + 3 < N_EDGES) {
        int4 s = *(const int4*)(ei + e4);
        int4 d = *(const int4*)(ei + N_EDGES + e4);
        int ss[4] = {s.x, s.y, s.z, s.w};
        int dd[4] = {d.x, d.y, d.z, d.w};
#pragma unroll
        for (int q = 0; q < 4; q++) {
            if ((unsigned)ss[q] < N_NODES && (unsigned)dd[q] < N_NODES) {
                int pos = atomicAdd(&g_cur[dd[q]], 1);
                if ((unsigned)pos < N_EDGES) {
                    float w = g_dinv[ss[q]] * g_dinv[dd[q]];
                    g_csr[pos] = make_int2(ss[q], __float_as_int(w));
                }
            }
        }
    }
}

// ---------------- wmma GEMM: g_h16 = fp16( A @ W16[widx] ) ----------------
// 256 threads = 8 warps, 128 rows/CTA. A staged through smem in 16-wide k-chunks
// (fp32->fp16 converted for a_sel=0), W staged once, padded rows for LDSM.
#define WLD 136   // Ws row stride (halfs)
#define ALD 24    // As row stride (halfs)
__global__ __launch_bounds__(256, 2) void k_gemm_w(const float* __restrict__ xin,
                                                   int a_sel, int widx) {
    __shared__ __align__(16) __half Ws[DIM * WLD];   // 34.8 KB (also C staging later)
    __shared__ __align__(16) __half As[DIM * ALD];   // 6 KB
    int tid = threadIdx.x;
    int wid = tid >> 5, lane = tid & 31;
    int r0 = blockIdx.x * 128;

    // load W tile into padded smem
    {
        const uint4* src = (const uint4*)g_w16[widx];
#pragma unroll
        for (int it = 0; it < 8; it++) {
            int i = tid + it * 256;          // uint4 index; 8 halfs each
            int row = i >> 4, col8 = (i & 15) << 3;
            *(uint4*)(Ws + row * WLD + col8) = src[i];
        }
    }

    wmma::fragment<wmma::accumulator, 16, 16, 16, float> acc[8];
#pragma unroll
    for (int n = 0; n < 8; n++) wmma::fill_fragment(acc[n], 0.f);

    int arow = tid >> 1;               // 0..127
    int acol = (tid & 1) << 3;         // 0 or 8

#pragma unroll
    for (int k = 0; k < 8; k++) {
        // stage A chunk [128 x 16] for columns k*16..k*16+15
        if (a_sel == 0) {
            int grow = r0 + arow;
            float4 v0 = make_float4(0.f, 0.f, 0.f, 0.f), v1 = v0;
            if (grow < N_NODES) {
                const float* p = xin + (size_t)grow * DIM + k * 16 + acol;
                v0 = *(const float4*)p;
                v1 = *(const float4*)(p + 4);
            }
            __half2 h0 = __floats2half2_rn(v0.x, v0.y);
            __half2 h1 = __floats2half2_rn(v0.z, v0.w);
            __half2 h2 = __floats2half2_rn(v1.x, v1.y);
            __half2 h3 = __floats2half2_rn(v1.z, v1.w);
            uint4 o;
            o.x = *(unsigned*)&h0; o.y = *(unsigned*)&h1;
            o.z = *(unsigned*)&h2; o.w = *(unsigned*)&h3;
            *(uint4*)(As + arow * ALD + acol) = o;
        } else {
            // fp16 source (g_h16b, padded to N_PAD; pad rows are zero)
            const uint4* p = (const uint4*)(g_h16b + (size_t)(r0 + arow) * DIM + k * 16 + acol);
            // acol is 0 or 8 halfs = 0 or 16B: one uint4 covers 8 halfs
            *(uint4*)(As + arow * ALD + acol) = *p;
        }
        __syncthreads();
        wmma::fragment<wmma::matrix_a, 16, 16, 16, __half, wmma::row_major> af;
        wmma::load_matrix_sync(af, As + wid * 16 * ALD, ALD);
#pragma unroll
        for (int n = 0; n < 8; n++) {
            wmma::fragment<wmma::matrix_b, 16, 16, 16, __half, wmma::row_major> bf;
            wmma::load_matrix_sync(bf, Ws + k * 16 * WLD + n * 16, WLD);
            wmma::mma_sync(acc[n], af, bf, acc[n]);
        }
        __syncthreads();
    }

    // epilogue: stage C in Ws region (8 warps x 16x64 f32 = 32 KB)
    float* Cs = (float*)Ws + wid * 1024;
    int wr0 = r0 + wid * 16;
#pragma unroll
    for (int h = 0; h < 2; h++) {
#pragma unroll
        for (int n = 0; n < 4; n++)
            wmma::store_matrix_sync(Cs + n * 16, acc[h * 4 + n], 64, wmma::mem_row_major);
        __syncwarp();
        int r = lane >> 1;
        int cb = (lane & 1) * 32;
        int grow = wr0 + r;
        if (grow < N_NODES) {
            const float* srcr = Cs + r * 64 + cb;
            __half* dstp = g_h16 + (size_t)grow * DIM + h * 64 + cb;
#pragma unroll
            for (int j = 0; j < 32; j += 8) {
                float4 v0 = *(const float4*)(srcr + j);
                float4 v1 = *(const float4*)(srcr + j + 4);
                __half2 h0 = __floats2half2_rn(v0.x, v0.y);
                __half2 h1 = __floats2half2_rn(v0.z, v0.w);
                __half2 h2 = __floats2half2_rn(v1.x, v1.y);
                __half2 h3 = __floats2half2_rn(v1.z, v1.w);
                uint4 o;
                o.x = *(unsigned*)&h0; o.y = *(unsigned*)&h1;
                o.z = *(unsigned*)&h2; o.w = *(unsigned*)&h3;
                *(uint4*)(dstp + j) = o;
            }
        }
        __syncwarp();
    }
}

// ---------------- edge aggregation (fp16 gather): one warp per dest node ----------
__global__ __launch_bounds__(256) void k_agg(int in_sel, int out_f16,
                                             const float* __restrict__ bias) {
    int n = (blockIdx.x * blockDim.x + threadIdx.x) >> 5;
    int lane = threadIdx.x & 31;
    if (n >= N_NODES) return;
    const uint2* in2 = (const uint2*)(in_sel ? g_h16b : g_h16);
    float dn = g_dinv[n];
    float sw = dn * dn;
    uint2 sv = in2[(size_t)n * 32 + lane];
    float2 sf0 = __half22float2(*(__half2*)&sv.x), sf1 = __half22float2(*(__half2*)&sv.y);
    float4 acc;
    acc.x = sw * sf0.x; acc.y = sw * sf0.y; acc.z = sw * sf1.x; acc.w = sw * sf1.y;
    int j = g_off[n];
    int end = j + g_cnt[n];
    for (; j + 4 <= end; j += 4) {
        int2 e0 = g_csr[j], e1 = g_csr[j + 1], e2 = g_csr[j + 2], e3 = g_csr[j + 3];
        float w0 = __int_as_float(e0.y), w1 = __int_as_float(e1.y);
        float w2 = __int_as_float(e2.y), w3 = __int_as_float(e3.y);
        uint2 r0 = in2[(size_t)e0.x * 32 + lane];
        uint2 r1 = in2[(size_t)e1.x * 32 + lane];
        uint2 r2 = in2[(size_t)e2.x * 32 + lane];
        uint2 r3 = in2[(size_t)e3.x * 32 + lane];
        float2 f0a = __half22float2(*(__half2*)&r0.x), f0b = __half22float2(*(__half2*)&r0.y);
        float2 f1a = __half22float2(*(__half2*)&r1.x), f1b = __half22float2(*(__half2*)&r1.y);
        float2 f2a = __half22float2(*(__half2*)&r2.x), f2b = __half22float2(*(__half2*)&r2.y);
        float2 f3a = __half22float2(*(__half2*)&r3.x), f3b = __half22float2(*(__half2*)&r3.y);
        acc.x += w0 * f0a.x; acc.y += w0 * f0a.y; acc.z += w0 * f0b.x; acc.w += w0 * f0b.y;
        acc.x += w1 * f1a.x; acc.y += w1 * f1a.y; acc.z += w1 * f1b.x; acc.w += w1 * f1b.y;
        acc.x += w2 * f2a.x; acc.y += w2 * f2a.y; acc.z += w2 * f2b.x; acc.w += w2 * f2b.y;
        acc.x += w3 * f3a.x; acc.y += w3 * f3a.y; acc.z += w3 * f3b.x; acc.w += w3 * f3b.y;
    }
    for (; j < end; j++) {
        int2 e = g_csr[j];
        float w = __int_as_float(e.y);
        uint2 r = in2[(size_t)e.x * 32 + lane];
        float2 fa = __half22float2(*(__half2*)&r.x), fb = __half22float2(*(__half2*)&r.y);
        acc.x += w * fa.x; acc.y += w * fa.y; acc.z += w * fb.x; acc.w += w * fb.y;
    }
    if (bias) {
        const float4 b = *(const float4*)(bias + lane * 4);
        acc.x = fmaxf(acc.x + b.x, 0.f);
        acc.y = fmaxf(acc.y + b.y, 0.f);
        acc.z = fmaxf(acc.z + b.z, 0.f);
        acc.w = fmaxf(acc.w + b.w, 0.f);
    }
    if (out_f16) {
        __half2 o0 = __floats2half2_rn(acc.x, acc.y);
        __half2 o1 = __floats2half2_rn(acc.z, acc.w);
        uint2 ov;
        ov.x = *(unsigned*)&o0; ov.y = *(unsigned*)&o1;
        ((uint2*)g_h16b)[(size_t)n * 32 + lane] = ov;
    } else {
        ((float4*)g_agg)[(size_t)n * 32 + lane] = acc;
    }
}

// ---------------- readout ----------------
#define NPB 256
__global__ void k_readout(const int* __restrict__ batch) {
    int d = threadIdx.x;
    int n0 = blockIdx.x * NPB;
    if (n0 >= N_NODES) return;
    int n1 = n0 + NPB;
    if (n1 > N_NODES) n1 = N_NODES;
    int curb = batch[n0];
    if ((unsigned)curb >= N_GRAPHS) curb = 0;
    float acc = 0.f;
    int c = 0;
    for (int n = n0; n < n1; n++) {
        int b = batch[n];
        if ((unsigned)b >= N_GRAPHS) b = 0;
        if (b != curb) {
            atomicAdd(&g_gsum[curb * DIM + d], acc);
            if (d == 0) atomicAdd(&g_gcnt[curb], (float)c);
            acc = 0.f; c = 0; curb = b;
        }
        acc += g_agg[(size_t)n * DIM + d];
        c++;
    }
    atomicAdd(&g_gsum[curb * DIM + d], acc);
    if (d == 0) atomicAdd(&g_gcnt[curb], (float)c);
}

// ---------------- final ----------------
__global__ __launch_bounds__(128) void k_final(const float* __restrict__ W3,
                                               const float* __restrict__ b3,
                                               float* __restrict__ out) {
    __shared__ float m[DIM];
    int g = blockIdx.x;
    int d = threadIdx.x;
    float c = g_gcnt[g];
    float inv = (c > 0.f) ? (1.f / c) : 0.f;
    m[d] = g_gsum[g * DIM + d] * inv;
    __syncthreads();
    float acc = 0.f;
#pragma unroll 8
    for (int k = 0; k < DIM; k++)
        acc = fmaf(m[k], W3[k * DIM + d], acc);
    out[g * DIM + d] = (c > 0.f) ? (acc + b3[d]) : 0.f;
}

// ---------------- launch ----------------
extern "C" void kernel_launch(void* const* d_in, const int* in_sizes, int n_in,
                              void* d_out, int out_size) {
    (void)in_sizes; (void)n_in; (void)out_size;
    const float* x     = (const float*)d_in[0];
    const int*   ei    = (const int*)d_in[1];
    const int*   batch = (const int*)d_in[2];
    const float* W1    = (const float*)d_in[3];
    const float* b1    = (const float*)d_in[4];
    const float* W2    = (const float*)d_in[5];
    const float* b2    = (const float*)d_in[6];
    const float* W3    = (const float*)d_in[7];
    const float* b3    = (const float*)d_in[8];
    float* out = (float*)d_out;

    int scan_blocks = (N_NODES + 4095) / 4096;
    int gemm_blocks = (N_NODES + 127) / 128;
    int agg_blocks = (N_NODES * 32 + 255) / 256;

    // order chosen so launch #4 (profiled slot) is k_gemm_w
    k_zero<<<(N_NODES + 255) / 256, 256>>>();                          // 1
    k_prepw<<<16, 256>>>(W1, W2);                                      // 2
    k_degree<<<(N_EDGES / 4 + 255) / 256, 256>>>(ei);                  // 3
    k_gemm_w<<<gemm_blocks, 256>>>(x, 0, 0);                           // 4 (profiled)
    k_scan1<<<scan_blocks, 1024>>>();                                  // 5
    k_scan3<<<(N_NODES + 255) / 256, 256>>>(scan_blocks);              // 6
    k_fill<<<(N_EDGES / 4 + 255) / 256, 256>>>(ei);                    // 7

    // layer 1: agg(g_h16) -> g_h16b fp16 with fused relu(.+b1)
    k_agg<<<agg_blocks, 256>>>(0, 1, b1);                              // 8
    // layer 2: gemm(g_h16b @ W2) -> g_h16 ; agg -> g_h16b fused relu(.+b2)
    k_gemm_w<<<gemm_blocks, 256>>>(x, 1, 1);                           // 9
    k_agg<<<agg_blocks, 256>>>(0, 1, b2);                              // 10
    // layer 3: agg(g_h16b) -> g_agg fp32 ; W3 post-pooling
    k_agg<<<agg_blocks, 256>>>(1, 0, nullptr);                         // 11

    k_readout<<<(N_NODES + NPB - 1) / NPB, 128>>>(batch);              // 12
    k_final<<<N_GRAPHS, 128>>>(W3, b3, out);                           // 13
}

// round 10
// speedup vs baseline: 1.2865x; 1.0392x over previous
#include <cuda_runtime.h>
#include <cuda_fp16.h>
#include <mma.h>
#include <cstdint>
#include <cstddef>

using namespace nvcuda;

#define N_NODES  100000
#define N_PAD    100096   // multiple of 128
#define N_EDGES  1600000
#define DIM      128
#define N_GRAPHS 512

// ---------------- scratch ----------------
__device__ __align__(16) __half g_h16[(size_t)N_NODES * DIM];   // GEMM out (gather src)
__device__ __align__(16) __half g_h16b[(size_t)N_PAD * DIM];    // agg out fp16 (GEMM A / layer3 src)
__device__ __align__(16) float  g_agg[(size_t)N_NODES * DIM];   // fp32 aggregated (readout src)
__device__ __align__(16) __half g_w16[2][DIM * DIM];            // fp16 W1, W2 row-major
__device__ __align__(16) float  g_dinv[N_NODES];
__device__ __align__(16) int    g_cnt[N_NODES];
__device__ __align__(16) int    g_off[N_NODES];
__device__ __align__(16) int    g_cur[N_NODES];
__device__ __align__(16) int2   g_csr[N_EDGES];
__device__ __align__(16) float  g_gsum[N_GRAPHS * DIM];
__device__ __align__(16) float  g_gcnt[N_GRAPHS];
__device__ int g_partial[32];

// ---------------- setup ----------------
__global__ void k_zero() {
    int i = blockIdx.x * blockDim.x + threadIdx.x;
    if (i < N_NODES) g_cnt[i] = 0;
    if (i < N_GRAPHS * DIM) g_gsum[i] = 0.f;
    if (i < N_GRAPHS) g_gcnt[i] = 0.f;
}

// 16 blocks: bit3 selects W, bits0-2 select 2048-elem chunk
__global__ __launch_bounds__(256) void k_prepw(const float* __restrict__ Wa,
                                               const float* __restrict__ Wb) {
    int w = blockIdx.x >> 3;
    const float* W = w ? Wb : Wa;
    __half* o = g_w16[w];
    int i = (blockIdx.x & 7) * 2048 + threadIdx.x * 8;
    float4 v0 = *(const float4*)(W + i);
    float4 v1 = *(const float4*)(W + i + 4);
    __half2 h0 = __floats2half2_rn(v0.x, v0.y);
    __half2 h1 = __floats2half2_rn(v0.z, v0.w);
    __half2 h2 = __floats2half2_rn(v1.x, v1.y);
    __half2 h3 = __floats2half2_rn(v1.z, v1.w);
    uint4 ov;
    ov.x = *(unsigned*)&h0; ov.y = *(unsigned*)&h1;
    ov.z = *(unsigned*)&h2; ov.w = *(unsigned*)&h3;
    *(uint4*)(o + i) = ov;
}

__global__ void k_degree(const int* __restrict__ ei) {
    int e4 = (blockIdx.x * blockDim.x + threadIdx.x) * 4;
    if (e4 + 3 < N_EDGES) {
        int4 d = *(const int4*)(ei + N_EDGES + e4);
        if ((unsigned)d.x < N_NODES) atomicAdd(&g_cnt[d.x], 1);
        if ((unsigned)d.y < N_NODES) atomicAdd(&g_cnt[d.y], 1);
        if ((unsigned)d.z < N_NODES) atomicAdd(&g_cnt[d.z], 1);
        if ((unsigned)d.w < N_NODES) atomicAdd(&g_cnt[d.w], 1);
    }
}

__global__ __launch_bounds__(1024) void k_scan1() {
    __shared__ int warp_sums[32];
    int t = threadIdx.x, lane = t & 31, wid = t >> 5;
    int i0 = blockIdx.x * 4096 + t * 4;
    int v[4];
#pragma unroll
    for (int q = 0; q < 4; q++) {
        int i = i0 + q;
        v[q] = (i < N_NODES) ? g_cnt[i] : 0;
        if (i < N_NODES) g_dinv[i] = rsqrtf((float)v[q] + 1.0f);
    }
    int tsum = v[0] + v[1] + v[2] + v[3];
    int x = tsum;
#pragma unroll
    for (int s = 1; s < 32; s <<= 1) {
        int y = __shfl_up_sync(0xffffffffu, x, s);
        if (lane >= s) x += y;
    }
    if (lane == 31) warp_sums[wid] = x;
    __syncthreads();
    if (wid == 0) {
        int ws = warp_sums[lane];
        int xx = ws;
#pragma unroll
        for (int s = 1; s < 32; s <<= 1) {
            int y = __shfl_up_sync(0xffffffffu, xx, s);
            if (lane >= s) xx += y;
        }
        warp_sums[lane] = xx - ws;
    }
    __syncthreads();
    int run = warp_sums[wid] + (x - tsum);
#pragma unroll
    for (int q = 0; q < 4; q++) {
        int i = i0 + q;
        if (i < N_NODES) g_off[i] = run;
        run += v[q];
    }
    if (t == 1023) g_partial[blockIdx.x] = warp_sums[31] + x;
}

__global__ void k_scan3(int nblk) {
    __shared__ int sp[32];
    int t = threadIdx.x;
    if (t < 32) {
        int v = (t < nblk) ? g_partial[t] : 0;
        int x = v;
#pragma unroll
        for (int s = 1; s < 32; s <<= 1) {
            int y = __shfl_up_sync(0xffffffffu, x, s);
            if ((t & 31) >= s) x += y;
        }
        sp[t] = x - v;
    }
    __syncthreads();
    int i = blockIdx.x * blockDim.x + t;
    if (i < N_NODES) {
        int o = g_off[i] + sp[i >> 12];
        g_off[i] = o;
        g_cur[i] = o;
    }
}

__global__ void k_fill(const int* __restrict__ ei) {
    int e4 = (blockIdx.x * blockDim.x + threadIdx.x) * 4;
    if (e4 + 3 < N_EDGES) {
        int4 s = *(const int4*)(ei + e4);
        int4 d = *(const int4*)(ei + N_EDGES + e4);
        int ss[4] = {s.x, s.y, s.z, s.w};
        int dd[4] = {d.x, d.y, d.z, d.w};
#pragma unroll
        for (int q = 0; q < 4; q++) {
            if ((unsigned)ss[q] < N_NODES && (unsigned)dd[q] < N_NODES) {
                int pos = atomicAdd(&g_cur[dd[q]], 1);
                if ((unsigned)pos < N_EDGES) {
                    float w = g_dinv[ss[q]] * g_dinv[dd[q]];
                    g_csr[pos] = make_int2(ss[q], __float_as_int(w));
                }
            }
        }
    }
}

// ---------------- wmma GEMM: g_h16 = fp16( A @ W16[widx] ) ----------------
// 256 threads = 8 warps, 128 rows/CTA. A and W tiles fully staged up front
// (single exposed global latency, MLP=16), one sync, then a pure MMA phase.
#define WLD 136   // Ws row stride (halfs)
#define XLD 136   // Xs (A tile) row stride (halfs)
__global__ __launch_bounds__(256, 2) void k_gemm_w(const float* __restrict__ xin,
                                                   int a_sel, int widx) {
    __shared__ __align__(16) __half Ws[DIM * WLD];   // 34.8 KB (C staging in epilogue)
    __shared__ __align__(16) __half Xs[DIM * XLD];   // 34.8 KB
    int tid = threadIdx.x;
    int wid = tid >> 5, lane = tid & 31;
    int r0 = blockIdx.x * 128;

    // ---- stage W tile (2048 uint4, 8 per thread) ----
    {
        const uint4* src = (const uint4*)g_w16[widx];
#pragma unroll
        for (int it = 0; it < 8; it++) {
            int i = tid + it * 256;              // uint4 idx; 8 halfs each
            int row = i >> 4, col8 = (i & 15) << 3;
            *(uint4*)(Ws + row * WLD + col8) = src[i];
        }
    }

    // ---- stage A tile ----
    if (a_sel == 0) {
        // fp32 source: 4096 float4 (16/thread), convert to fp16, store uint2
        const float4* x4 = (const float4*)(xin + (size_t)r0 * DIM);
        bool full = (r0 + 128) <= N_NODES;
#pragma unroll
        for (int it = 0; it < 16; it++) {
            int j = tid + it * 256;              // float4 idx
            int row = j >> 5, col4 = (j & 31) << 2;
            float4 v = make_float4(0.f, 0.f, 0.f, 0.f);
            if (full || (r0 + row) < N_NODES) v = x4[j];
            __half2 h0 = __floats2half2_rn(v.x, v.y);
            __half2 h1 = __floats2half2_rn(v.z, v.w);
            uint2 o;
            o.x = *(unsigned*)&h0; o.y = *(unsigned*)&h1;
            *(uint2*)(Xs + row * XLD + col4) = o;
        }
    } else {
        // fp16 source (g_h16b padded to N_PAD, pad rows zero): 2048 uint4 (8/thread)
        const uint4* src = (const uint4*)(g_h16b + (size_t)r0 * DIM);
#pragma unroll
        for (int it = 0; it < 8; it++) {
            int i = tid + it * 256;
            int row = i >> 4, col8 = (i & 15) << 3;
            *(uint4*)(Xs + row * XLD + col8) = src[i];
        }
    }
    __syncthreads();

    // ---- MMA phase: no syncs ----
    wmma::fragment<wmma::accumulator, 16, 16, 16, float> acc[8];
#pragma unroll
    for (int n = 0; n < 8; n++) wmma::fill_fragment(acc[n], 0.f);
#pragma unroll
    for (int k = 0; k < 8; k++) {
        wmma::fragment<wmma::matrix_a, 16, 16, 16, __half, wmma::row_major> af;
        wmma::load_matrix_sync(af, Xs + (wid * 16) * XLD + k * 16, XLD);
#pragma unroll
        for (int n = 0; n < 8; n++) {
            wmma::fragment<wmma::matrix_b, 16, 16, 16, __half, wmma::row_major> bf;
            wmma::load_matrix_sync(bf, Ws + (k * 16) * WLD + n * 16, WLD);
            wmma::mma_sync(acc[n], af, bf, acc[n]);
        }
    }
    __syncthreads();  // everyone done reading Ws; reuse as C staging

    // ---- epilogue: per-warp C staging (8 warps x 16x64 f32 = 32 KB in Ws) ----
    float* Cs = (float*)Ws + wid * 1024;
    int wr0 = r0 + wid * 16;
#pragma unroll
    for (int h = 0; h < 2; h++) {
#pragma unroll
        for (int n = 0; n < 4; n++)
            wmma::store_matrix_sync(Cs + n * 16, acc[h * 4 + n], 64, wmma::mem_row_major);
        __syncwarp();
        int r = lane >> 1;
        int cb = (lane & 1) * 32;
        int grow = wr0 + r;
        if (grow < N_NODES) {
            const float* srcr = Cs + r * 64 + cb;
            __half* dstp = g_h16 + (size_t)grow * DIM + h * 64 + cb;
#pragma unroll
            for (int j = 0; j < 32; j += 8) {
                float4 v0 = *(const float4*)(srcr + j);
                float4 v1 = *(const float4*)(srcr + j + 4);
                __half2 h0 = __floats2half2_rn(v0.x, v0.y);
                __half2 h1 = __floats2half2_rn(v0.z, v0.w);
                __half2 h2 = __floats2half2_rn(v1.x, v1.y);
                __half2 h3 = __floats2half2_rn(v1.z, v1.w);
                uint4 o;
                o.x = *(unsigned*)&h0; o.y = *(unsigned*)&h1;
                o.z = *(unsigned*)&h2; o.w = *(unsigned*)&h3;
                *(uint4*)(dstp + j) = o;
            }
        }
        __syncwarp();
    }
}

// ---------------- edge aggregation (fp16 gather): one warp per dest node ----------
__global__ __launch_bounds__(256) void k_agg(int in_sel, int out_f16,
                                             const float* __restrict__ bias) {
    int n = (blockIdx.x * blockDim.x + threadIdx.x) >> 5;
    int lane = threadIdx.x & 31;
    if (n >= N_NODES) return;
    const uint2* in2 = (const uint2*)(in_sel ? g_h16b : g_h16);
    float dn = g_dinv[n];
    float sw = dn * dn;
    uint2 sv = in2[(size_t)n * 32 + lane];
    float2 sf0 = __half22float2(*(__half2*)&sv.x), sf1 = __half22float2(*(__half2*)&sv.y);
    float4 acc;
    acc.x = sw * sf0.x; acc.y = sw * sf0.y; acc.z = sw * sf1.x; acc.w = sw * sf1.y;
    int j = g_off[n];
    int end = j + g_cnt[n];
    for (; j + 4 <= end; j += 4) {
        int2 e0 = g_csr[j], e1 = g_csr[j + 1], e2 = g_csr[j + 2], e3 = g_csr[j + 3];
        float w0 = __int_as_float(e0.y), w1 = __int_as_float(e1.y);
        float w2 = __int_as_float(e2.y), w3 = __int_as_float(e3.y);
        uint2 r0 = in2[(size_t)e0.x * 32 + lane];
        uint2 r1 = in2[(size_t)e1.x * 32 + lane];
        uint2 r2 = in2[(size_t)e2.x * 32 + lane];
        uint2 r3 = in2[(size_t)e3.x * 32 + lane];
        float2 f0a = __half22float2(*(__half2*)&r0.x), f0b = __half22float2(*(__half2*)&r0.y);
        float2 f1a = __half22float2(*(__half2*)&r1.x), f1b = __half22float2(*(__half2*)&r1.y);
        float2 f2a = __half22float2(*(__half2*)&r2.x), f2b = __half22float2(*(__half2*)&r2.y);
        float2 f3a = __half22float2(*(__half2*)&r3.x), f3b = __half22float2(*(__half2*)&r3.y);
        acc.x += w0 * f0a.x; acc.y += w0 * f0a.y; acc.z += w0 * f0b.x; acc.w += w0 * f0b.y;
        acc.x += w1 * f1a.x; acc.y += w1 * f1a.y; acc.z += w1 * f1b.x; acc.w += w1 * f1b.y;
        acc.x += w2 * f2a.x; acc.y += w2 * f2a.y; acc.z += w2 * f2b.x; acc.w += w2 * f2b.y;
        acc.x += w3 * f3a.x; acc.y += w3 * f3a.y; acc.z += w3 * f3b.x; acc.w += w3 * f3b.y;
    }
    for (; j < end; j++) {
        int2 e = g_csr[j];
        float w = __int_as_float(e.y);
        uint2 r = in2[(size_t)e.x * 32 + lane];
        float2 fa = __half22float2(*(__half2*)&r.x), fb = __half22float2(*(__half2*)&r.y);
        acc.x += w * fa.x; acc.y += w * fa.y; acc.z += w * fb.x; acc.w += w * fb.y;
    }
    if (bias) {
        const float4 b = *(const float4*)(bias + lane * 4);
        acc.x = fmaxf(acc.x + b.x, 0.f);
        acc.y = fmaxf(acc.y + b.y, 0.f);
        acc.z = fmaxf(acc.z + b.z, 0.f);
        acc.w = fmaxf(acc.w + b.w, 0.f);
    }
    if (out_f16) {
        __half2 o0 = __floats2half2_rn(acc.x, acc.y);
        __half2 o1 = __floats2half2_rn(acc.z, acc.w);
        uint2 ov;
        ov.x = *(unsigned*)&o0; ov.y = *(unsigned*)&o1;
        ((uint2*)g_h16b)[(size_t)n * 32 + lane] = ov;
    } else {
        ((float4*)g_agg)[(size_t)n * 32 + lane] = acc;
    }
}

// ---------------- readout ----------------
#define NPB 256
__global__ void k_readout(const int* __restrict__ batch) {
    int d = threadIdx.x;
    int n0 = blockIdx.x * NPB;
    if (n0 >= N_NODES) return;
    int n1 = n0 + NPB;
    if (n1 > N_NODES) n1 = N_NODES;
    int curb = batch[n0];
    if ((unsigned)curb >= N_GRAPHS) curb = 0;
    float acc = 0.f;
    int c = 0;
    for (int n = n0; n < n1; n++) {
        int b = batch[n];
        if ((unsigned)b >= N_GRAPHS) b = 0;
        if (b != curb) {
            atomicAdd(&g_gsum[curb * DIM + d], acc);
            if (d == 0) atomicAdd(&g_gcnt[curb], (float)c);
            acc = 0.f; c = 0; curb = b;
        }
        acc += g_agg[(size_t)n * DIM + d];
        c++;
    }
    atomicAdd(&g_gsum[curb * DIM + d], acc);
    if (d == 0) atomicAdd(&g_gcnt[curb], (float)c);
}

// ---------------- final ----------------
__global__ __launch_bounds__(128) void k_final(const float* __restrict__ W3,
                                               const float* __restrict__ b3,
                                               float* __restrict__ out) {
    __shared__ float m[DIM];
    int g = blockIdx.x;
    int d = threadIdx.x;
    float c = g_gcnt[g];
    float inv = (c > 0.f) ? (1.f / c) : 0.f;
    m[d] = g_gsum[g * DIM + d] * inv;
    __syncthreads();
    float acc = 0.f;
#pragma unroll 8
    for (int k = 0; k < DIM; k++)
        acc = fmaf(m[k], W3[k * DIM + d], acc);
    out[g * DIM + d] = (c > 0.f) ? (acc + b3[d]) : 0.f;
}

// ---------------- launch ----------------
extern "C" void kernel_launch(void* const* d_in, const int* in_sizes, int n_in,
                              void* d_out, int out_size) {
    (void)in_sizes; (void)n_in; (void)out_size;
    const float* x     = (const float*)d_in[0];
    const int*   ei    = (const int*)d_in[1];
    const int*   batch = (const int*)d_in[2];
    const float* W1    = (const float*)d_in[3];
    const float* b1    = (const float*)d_in[4];
    const float* W2    = (const float*)d_in[5];
    const float* b2    = (const float*)d_in[6];
    const float* W3    = (const float*)d_in[7];
    const float* b3    = (const float*)d_in[8];
    float* out = (float*)d_out;

    int scan_blocks = (N_NODES + 4095) / 4096;
    int gemm_blocks = (N_NODES + 127) / 128;
    int agg_blocks = (N_NODES * 32 + 255) / 256;

    // order chosen so launch #4 (profiled slot) is k_gemm_w
    k_zero<<<(N_NODES + 255) / 256, 256>>>();                          // 1
    k_prepw<<<16, 256>>>(W1, W2);                                      // 2
    k_degree<<<(N_EDGES / 4 + 255) / 256, 256>>>(ei);                  // 3
    k_gemm_w<<<gemm_blocks, 256>>>(x, 0, 0);                           // 4 (profiled)
    k_scan1<<<scan_blocks, 1024>>>();                                  // 5
    k_scan3<<<(N_NODES + 255) / 256, 256>>>(scan_blocks);              // 6
    k_fill<<<(N_EDGES / 4 + 255) / 256, 256>>>(ei);                    // 7

    // layer 1: agg(g_h16) -> g_h16b fp16 with fused relu(.+b1)
    k_agg<<<agg_blocks, 256>>>(0, 1, b1);                              // 8
    // layer 2: gemm(g_h16b @ W2) -> g_h16 ; agg -> g_h16b fused relu(.+b2)
    k_gemm_w<<<gemm_blocks, 256>>>(x, 1, 1);                           // 9
    k_agg<<<agg_blocks, 256>>>(0, 1, b2);                              // 10
    // layer 3: agg(g_h16b) -> g_agg fp32 ; W3 post-pooling
    k_agg<<<agg_blocks, 256>>>(1, 0, nullptr);                         // 11

    k_readout<<<(N_NODES + NPB - 1) / NPB, 128>>>(batch);              // 12
    k_final<<<N_GRAPHS, 128>>>(W3, b3, out);                           // 13
}

// round 11
// speedup vs baseline: 1.3551x; 1.0533x over previous
#include <cuda_runtime.h>
#include <cuda_fp16.h>
#include <mma.h>
#include <cstdint>
#include <cstddef>

using namespace nvcuda;

#define N_NODES  100000
#define N_PAD    100096   // multiple of 128
#define N_EDGES  1600000
#define DIM      128
#define N_GRAPHS 512

// ---------------- scratch ----------------
__device__ __align__(16) __half g_h16[(size_t)N_NODES * DIM];   // GEMM out, pre-scaled by dinv (gather src)
__device__ __align__(16) __half g_h16b[(size_t)N_PAD * DIM];    // agg out fp16
__device__ __align__(16) float  g_agg[(size_t)N_NODES * DIM];   // fp32 aggregated (readout src)
__device__ __align__(16) __half g_w16[2][DIM * DIM];            // fp16 W1, W2 row-major
__device__ __align__(16) float  g_dinv[N_NODES];
__device__ __align__(16) int    g_cnt[N_NODES];
__device__ __align__(16) int    g_off[N_NODES];
__device__ __align__(16) int    g_cur[N_NODES];
__device__ __align__(16) int    g_csr_i[N_EDGES];               // src index only
__device__ __align__(16) float  g_gsum[N_GRAPHS * DIM];
__device__ __align__(16) float  g_gcnt[N_GRAPHS];
__device__ int g_partial[32];

// ---------------- setup ----------------
__global__ void k_zero() {
    int i = blockIdx.x * blockDim.x + threadIdx.x;
    if (i < N_NODES) g_cnt[i] = 0;
    if (i < N_GRAPHS * DIM) g_gsum[i] = 0.f;
    if (i < N_GRAPHS) g_gcnt[i] = 0.f;
}

__global__ __launch_bounds__(256) void k_prepw(const float* __restrict__ Wa,
                                               const float* __restrict__ Wb) {
    int w = blockIdx.x >> 3;
    const float* W = w ? Wb : Wa;
    __half* o = g_w16[w];
    int i = (blockIdx.x & 7) * 2048 + threadIdx.x * 8;
    float4 v0 = *(const float4*)(W + i);
    float4 v1 = *(const float4*)(W + i + 4);
    __half2 h0 = __floats2half2_rn(v0.x, v0.y);
    __half2 h1 = __floats2half2_rn(v0.z, v0.w);
    __half2 h2 = __floats2half2_rn(v1.x, v1.y);
    __half2 h3 = __floats2half2_rn(v1.z, v1.w);
    uint4 ov;
    ov.x = *(unsigned*)&h0; ov.y = *(unsigned*)&h1;
    ov.z = *(unsigned*)&h2; ov.w = *(unsigned*)&h3;
    *(uint4*)(o + i) = ov;
}

__global__ void k_degree(const int* __restrict__ ei) {
    int e4 = (blockIdx.x * blockDim.x + threadIdx.x) * 4;
    if (e4 + 3 < N_EDGES) {
        int4 d = *(const int4*)(ei + N_EDGES + e4);
        if ((unsigned)d.x < N_NODES) atomicAdd(&g_cnt[d.x], 1);
        if ((unsigned)d.y < N_NODES) atomicAdd(&g_cnt[d.y], 1);
        if ((unsigned)d.z < N_NODES) atomicAdd(&g_cnt[d.z], 1);
        if ((unsigned)d.w < N_NODES) atomicAdd(&g_cnt[d.w], 1);
    }
}

__global__ __launch_bounds__(1024) void k_scan1() {
    __shared__ int warp_sums[32];
    int t = threadIdx.x, lane = t & 31, wid = t >> 5;
    int i0 = blockIdx.x * 4096 + t * 4;
    int v[4];
#pragma unroll
    for (int q = 0; q < 4; q++) {
        int i = i0 + q;
        v[q] = (i < N_NODES) ? g_cnt[i] : 0;
        if (i < N_NODES) g_dinv[i] = rsqrtf((float)v[q] + 1.0f);
    }
    int tsum = v[0] + v[1] + v[2] + v[3];
    int x = tsum;
#pragma unroll
    for (int s = 1; s < 32; s <<= 1) {
        int y = __shfl_up_sync(0xffffffffu, x, s);
        if (lane >= s) x += y;
    }
    if (lane == 31) warp_sums[wid] = x;
    __syncthreads();
    if (wid == 0) {
        int ws = warp_sums[lane];
        int xx = ws;
#pragma unroll
        for (int s = 1; s < 32; s <<= 1) {
            int y = __shfl_up_sync(0xffffffffu, xx, s);
            if (lane >= s) xx += y;
        }
        warp_sums[lane] = xx - ws;
    }
    __syncthreads();
    int run = warp_sums[wid] + (x - tsum);
#pragma unroll
    for (int q = 0; q < 4; q++) {
        int i = i0 + q;
        if (i < N_NODES) g_off[i] = run;
        run += v[q];
    }
    if (t == 1023) g_partial[blockIdx.x] = warp_sums[31] + x;
}

__global__ void k_scan3(int nblk) {
    __shared__ int sp[32];
    int t = threadIdx.x;
    if (t < 32) {
        int v = (t < nblk) ? g_partial[t] : 0;
        int x = v;
#pragma unroll
        for (int s = 1; s < 32; s <<= 1) {
            int y = __shfl_up_sync(0xffffffffu, x, s);
            if ((t & 31) >= s) x += y;
        }
        sp[t] = x - v;
    }
    __syncthreads();
    int i = blockIdx.x * blockDim.x + t;
    if (i < N_NODES) {
        int o = g_off[i] + sp[i >> 12];
        g_off[i] = o;
        g_cur[i] = o;
    }
}

__global__ void k_fill(const int* __restrict__ ei) {
    int e4 = (blockIdx.x * blockDim.x + threadIdx.x) * 4;
    if (e4 + 3 < N_EDGES) {
        int4 s = *(const int4*)(ei + e4);
        int4 d = *(const int4*)(ei + N_EDGES + e4);
        int ss[4] = {s.x, s.y, s.z, s.w};
        int dd[4] = {d.x, d.y, d.z, d.w};
#pragma unroll
        for (int q = 0; q < 4; q++) {
            if ((unsigned)ss[q] < N_NODES && (unsigned)dd[q] < N_NODES) {
                int pos = atomicAdd(&g_cur[dd[q]], 1);
                if ((unsigned)pos < N_EDGES) g_csr_i[pos] = ss[q];
            }
        }
    }
}

// ---------------- wmma GEMM: g_h16 = fp16( dinv[row] * (A @ W16[widx]) ) ------------
#define WLD 136
#define XLD 136
__global__ __launch_bounds__(256, 2) void k_gemm_w(const float* __restrict__ xin,
                                                   int a_sel, int widx) {
    __shared__ __align__(16) __half Ws[DIM * WLD];
    __shared__ __align__(16) __half Xs[DIM * XLD];
    int tid = threadIdx.x;
    int wid = tid >> 5, lane = tid & 31;
    int r0 = blockIdx.x * 128;

    {
        const uint4* src = (const uint4*)g_w16[widx];
#pragma unroll
        for (int it = 0; it < 8; it++) {
            int i = tid + it * 256;
            int row = i >> 4, col8 = (i & 15) << 3;
            *(uint4*)(Ws + row * WLD + col8) = src[i];
        }
    }

    if (a_sel == 0) {
        const float4* x4 = (const float4*)(xin + (size_t)r0 * DIM);
        bool full = (r0 + 128) <= N_NODES;
#pragma unroll
        for (int it = 0; it < 16; it++) {
            int j = tid + it * 256;
            int row = j >> 5, col4 = (j & 31) << 2;
            float4 v = make_float4(0.f, 0.f, 0.f, 0.f);
            if (full || (r0 + row) < N_NODES) v = x4[j];
            __half2 h0 = __floats2half2_rn(v.x, v.y);
            __half2 h1 = __floats2half2_rn(v.z, v.w);
            uint2 o;
            o.x = *(unsigned*)&h0; o.y = *(unsigned*)&h1;
            *(uint2*)(Xs + row * XLD + col4) = o;
        }
    } else {
        const uint4* src = (const uint4*)(g_h16b + (size_t)r0 * DIM);
#pragma unroll
        for (int it = 0; it < 8; it++) {
            int i = tid + it * 256;
            int row = i >> 4, col8 = (i & 15) << 3;
            *(uint4*)(Xs + row * XLD + col8) = src[i];
        }
    }
    __syncthreads();

    wmma::fragment<wmma::accumulator, 16, 16, 16, float> acc[8];
#pragma unroll
    for (int n = 0; n < 8; n++) wmma::fill_fragment(acc[n], 0.f);
#pragma unroll
    for (int k = 0; k < 8; k++) {
        wmma::fragment<wmma::matrix_a, 16, 16, 16, __half, wmma::row_major> af;
        wmma::load_matrix_sync(af, Xs + (wid * 16) * XLD + k * 16, XLD);
#pragma unroll
        for (int n = 0; n < 8; n++) {
            wmma::fragment<wmma::matrix_b, 16, 16, 16, __half, wmma::row_major> bf;
            wmma::load_matrix_sync(bf, Ws + (k * 16) * WLD + n * 16, WLD);
            wmma::mma_sync(acc[n], af, bf, acc[n]);
        }
    }
    __syncthreads();

    float* Cs = (float*)Ws + wid * 1024;
    int wr0 = r0 + wid * 16;
#pragma unroll
    for (int h = 0; h < 2; h++) {
#pragma unroll
        for (int n = 0; n < 4; n++)
            wmma::store_matrix_sync(Cs + n * 16, acc[h * 4 + n], 64, wmma::mem_row_major);
        __syncwarp();
        int r = lane >> 1;
        int cb = (lane & 1) * 32;
        int grow = wr0 + r;
        if (grow < N_NODES) {
            float dv = g_dinv[grow];
            const float* srcr = Cs + r * 64 + cb;
            __half* dstp = g_h16 + (size_t)grow * DIM + h * 64 + cb;
#pragma unroll
            for (int j = 0; j < 32; j += 8) {
                float4 v0 = *(const float4*)(srcr + j);
                float4 v1 = *(const float4*)(srcr + j + 4);
                __half2 h0 = __floats2half2_rn(v0.x * dv, v0.y * dv);
                __half2 h1 = __floats2half2_rn(v0.z * dv, v0.w * dv);
                __half2 h2 = __floats2half2_rn(v1.x * dv, v1.y * dv);
                __half2 h3 = __floats2half2_rn(v1.z * dv, v1.w * dv);
                uint4 o;
                o.x = *(unsigned*)&h0; o.y = *(unsigned*)&h1;
                o.z = *(unsigned*)&h2; o.w = *(unsigned*)&h3;
                *(uint4*)(dstp + j) = o;
            }
        }
        __syncwarp();
    }
}

// ---------------- edge aggregation: half-warp per edge, LDG.128 --------------------
// Gather-source rows are pre-scaled by dinv[src]. Result: acc_true = dn * sum.
// out: fp32 g_agg (acc_true), or fp16 g_h16b = [relu(acc_true + bias)] [* dn if out_scale]
__device__ __forceinline__ void acc_row(float* acc, const uint4& r) {
    float2 f0 = __half22float2(*(__half2*)&r.x);
    float2 f1 = __half22float2(*(__half2*)&r.y);
    float2 f2 = __half22float2(*(__half2*)&r.z);
    float2 f3 = __half22float2(*(__half2*)&r.w);
    acc[0] += f0.x; acc[1] += f0.y; acc[2] += f1.x; acc[3] += f1.y;
    acc[4] += f2.x; acc[5] += f2.y; acc[6] += f3.x; acc[7] += f3.y;
}

__global__ __launch_bounds__(256) void k_agg(int in_sel, int out_f16, int out_scale,
                                             const float* __restrict__ bias) {
    int n = (blockIdx.x * blockDim.x + threadIdx.x) >> 5;
    int lane = threadIdx.x & 31;
    if (n >= N_NODES) return;
    int half = lane >> 4, hl = lane & 15;
    const uint4* in4 = (const uint4*)(in_sel ? g_h16b : g_h16);
    float dn = g_dinv[n];

    float acc[8];
    {
        uint4 sv = in4[(size_t)n * 16 + hl];   // self row (already scaled by dinv[n])
        float2 f0 = __half22float2(*(__half2*)&sv.x);
        float2 f1 = __half22float2(*(__half2*)&sv.y);
        float2 f2 = __half22float2(*(__half2*)&sv.z);
        float2 f3 = __half22float2(*(__half2*)&sv.w);
        float m = (half == 0) ? 1.f : 0.f;     // count self once
        acc[0] = m * f0.x; acc[1] = m * f0.y; acc[2] = m * f1.x; acc[3] = m * f1.y;
        acc[4] = m * f2.x; acc[5] = m * f2.y; acc[6] = m * f3.x; acc[7] = m * f3.y;
    }

    int j = g_off[n];
    int end = j + g_cnt[n];
    for (; j + 8 <= end; j += 8) {
        int s0 = g_csr_i[j + half];
        int s1 = g_csr_i[j + 2 + half];
        int s2 = g_csr_i[j + 4 + half];
        int s3 = g_csr_i[j + 6 + half];
        uint4 r0 = in4[(size_t)s0 * 16 + hl];
        uint4 r1 = in4[(size_t)s1 * 16 + hl];
        uint4 r2 = in4[(size_t)s2 * 16 + hl];
        uint4 r3 = in4[(size_t)s3 * 16 + hl];
        acc_row(acc, r0); acc_row(acc, r1); acc_row(acc, r2); acc_row(acc, r3);
    }
    for (; j + 2 <= end; j += 2) {
        int s = g_csr_i[j + half];
        uint4 r = in4[(size_t)s * 16 + hl];
        acc_row(acc, r);
    }
    if (j + half < end) {
        int s = g_csr_i[j + half];
        uint4 r = in4[(size_t)s * 16 + hl];
        acc_row(acc, r);
    }

    // combine halves
#pragma unroll
    for (int q = 0; q < 8; q++) acc[q] += __shfl_xor_sync(0xffffffffu, acc[q], 16);

    if (half == 0) {
#pragma unroll
        for (int q = 0; q < 8; q++) acc[q] *= dn;
        if (bias) {
            float4 b0 = *(const float4*)(bias + hl * 8);
            float4 b1 = *(const float4*)(bias + hl * 8 + 4);
            acc[0] = fmaxf(acc[0] + b0.x, 0.f); acc[1] = fmaxf(acc[1] + b0.y, 0.f);
            acc[2] = fmaxf(acc[2] + b0.z, 0.f); acc[3] = fmaxf(acc[3] + b0.w, 0.f);
            acc[4] = fmaxf(acc[4] + b1.x, 0.f); acc[5] = fmaxf(acc[5] + b1.y, 0.f);
            acc[6] = fmaxf(acc[6] + b1.z, 0.f); acc[7] = fmaxf(acc[7] + b1.w, 0.f);
        }
        if (out_scale) {
#pragma unroll
            for (int q = 0; q < 8; q++) acc[q] *= dn;
        }
        if (out_f16) {
            __half2 h0 = __floats2half2_rn(acc[0], acc[1]);
            __half2 h1 = __floats2half2_rn(acc[2], acc[3]);
            __half2 h2 = __floats2half2_rn(acc[4], acc[5]);
            __half2 h3 = __floats2half2_rn(acc[6], acc[7]);
            uint4 o;
            o.x = *(unsigned*)&h0; o.y = *(unsigned*)&h1;
            o.z = *(unsigned*)&h2; o.w = *(unsigned*)&h3;
            *(uint4*)(g_h16b + (size_t)n * DIM + hl * 8) = o;
        } else {
            float* dst = g_agg + (size_t)n * DIM + hl * 8;
            *(float4*)(dst + 0) = make_float4(acc[0], acc[1], acc[2], acc[3]);
            *(float4*)(dst + 4) = make_float4(acc[4], acc[5], acc[6], acc[7]);
        }
    }
}

// ---------------- readout ----------------
#define NPB 256
__global__ void k_readout(const int* __restrict__ batch) {
    int d = threadIdx.x;
    int n0 = blockIdx.x * NPB;
    if (n0 >= N_NODES) return;
    int n1 = n0 + NPB;
    if (n1 > N_NODES) n1 = N_NODES;
    int curb = batch[n0];
    if ((unsigned)curb >= N_GRAPHS) curb = 0;
    float acc = 0.f;
    int c = 0;
    for (int n = n0; n < n1; n++) {
        int b = batch[n];
        if ((unsigned)b >= N_GRAPHS) b = 0;
        if (b != curb) {
            atomicAdd(&g_gsum[curb * DIM + d], acc);
            if (d == 0) atomicAdd(&g_gcnt[curb], (float)c);
            acc = 0.f; c = 0; curb = b;
        }
        acc += g_agg[(size_t)n * DIM + d];
        c++;
    }
    atomicAdd(&g_gsum[curb * DIM + d], acc);
    if (d == 0) atomicAdd(&g_gcnt[curb], (float)c);
}

// ---------------- final ----------------
__global__ __launch_bounds__(128) void k_final(const float* __restrict__ W3,
                                               const float* __restrict__ b3,
                                               float* __restrict__ out) {
    __shared__ float m[DIM];
    int g = blockIdx.x;
    int d = threadIdx.x;
    float c = g_gcnt[g];
    float inv = (c > 0.f) ? (1.f / c) : 0.f;
    m[d] = g_gsum[g * DIM + d] * inv;
    __syncthreads();
    float acc = 0.f;
#pragma unroll 8
    for (int k = 0; k < DIM; k++)
        acc = fmaf(m[k], W3[k * DIM + d], acc);
    out[g * DIM + d] = (c > 0.f) ? (acc + b3[d]) : 0.f;
}

// ---------------- launch ----------------
extern "C" void kernel_launch(void* const* d_in, const int* in_sizes, int n_in,
                              void* d_out, int out_size) {
    (void)in_sizes; (void)n_in; (void)out_size;
    const float* x     = (const float*)d_in[0];
    const int*   ei    = (const int*)d_in[1];
    const int*   batch = (const int*)d_in[2];
    const float* W1    = (const float*)d_in[3];
    const float* b1    = (const float*)d_in[4];
    const float* W2    = (const float*)d_in[5];
    const float* b2    = (const float*)d_in[6];
    const float* W3    = (const float*)d_in[7];
    const float* b3    = (const float*)d_in[8];
    float* out = (float*)d_out;

    int scan_blocks = (N_NODES + 4095) / 4096;
    int gemm_blocks = (N_NODES + 127) / 128;
    int agg_blocks = (N_NODES * 32 + 255) / 256;

    k_prepw<<<16, 256>>>(W1, W2);                                      // 1
    k_zero<<<(N_NODES + 255) / 256, 256>>>();                          // 2
    k_degree<<<(N_EDGES / 4 + 255) / 256, 256>>>(ei);                  // 3
    k_scan1<<<scan_blocks, 1024>>>();                                  // 4 (profiled)
    k_scan3<<<(N_NODES + 255) / 256, 256>>>(scan_blocks);              // 5
    k_gemm_w<<<gemm_blocks, 256>>>(x, 0, 0);                           // 6
    k_fill<<<(N_EDGES / 4 + 255) / 256, 256>>>(ei);                    // 7

    // layer 1: agg(g_h16) -> g_h16b = relu(dn*acc + b1)   (unscaled; feeds gemm2)
    k_agg<<<agg_blocks, 256>>>(0, 1, 0, b1);                           // 8
    // layer 2: gemm2 -> g_h16 (scaled) ; agg -> g_h16b = relu(dn*acc + b2) * dn (scaled)
    k_gemm_w<<<gemm_blocks, 256>>>(x, 1, 1);                           // 9
    k_agg<<<agg_blocks, 256>>>(0, 1, 1, b2);                           // 10
    // layer 3: agg(g_h16b) -> g_agg = dn*acc (fp32)
    k_agg<<<agg_blocks, 256>>>(1, 0, 0, nullptr);                      // 11

    k_readout<<<(N_NODES + NPB - 1) / NPB, 128>>>(batch);              // 12
    k_final<<<N_GRAPHS, 128>>>(W3, b3, out);                           // 13
}

// round 12
// speedup vs baseline: 1.4628x; 1.0795x over previous
#include <cuda_runtime.h>
#include <cuda_fp16.h>
#include <mma.h>
#include <cstdint>
#include <cstddef>

using namespace nvcuda;

#define N_NODES  100000
#define N_PAD    100096   // multiple of 128
#define N_EDGES  1600000
#define DIM      128
#define N_GRAPHS 512

// ---------------- scratch ----------------
__device__ __align__(16) __half g_h16[(size_t)N_NODES * DIM];   // gemm out / agg3 out
__device__ __align__(16) __half g_h16b[(size_t)N_PAD * DIM];    // agg1/agg2 out (gemm2 A)
__device__ __align__(16) __half g_w16[2][DIM * DIM];            // fp16 W1, W2 row-major
__device__ __align__(16) float  g_dinv[N_NODES];
__device__ __align__(16) int    g_cnt[N_NODES];
__device__ __align__(16) int    g_off[N_NODES];
__device__ __align__(16) int    g_cur[N_NODES];
__device__ __align__(16) int    g_csr_i[N_EDGES];               // src index only
__device__ __align__(16) float  g_gsum[N_GRAPHS * DIM];
__device__ __align__(16) float  g_gcnt[N_GRAPHS];
__device__ int g_partial[32];

// ---------------- setup ----------------
__global__ void k_zero() {
    int i = blockIdx.x * blockDim.x + threadIdx.x;
    if (i < N_NODES) g_cnt[i] = 0;
    if (i < N_GRAPHS * DIM) g_gsum[i] = 0.f;
    if (i < N_GRAPHS) g_gcnt[i] = 0.f;
}

__global__ __launch_bounds__(256) void k_prepw(const float* __restrict__ Wa,
                                               const float* __restrict__ Wb) {
    int w = blockIdx.x >> 3;
    const float* W = w ? Wb : Wa;
    __half* o = g_w16[w];
    int i = (blockIdx.x & 7) * 2048 + threadIdx.x * 8;
    float4 v0 = *(const float4*)(W + i);
    float4 v1 = *(const float4*)(W + i + 4);
    __half2 h0 = __floats2half2_rn(v0.x, v0.y);
    __half2 h1 = __floats2half2_rn(v0.z, v0.w);
    __half2 h2 = __floats2half2_rn(v1.x, v1.y);
    __half2 h3 = __floats2half2_rn(v1.z, v1.w);
    uint4 ov;
    ov.x = *(unsigned*)&h0; ov.y = *(unsigned*)&h1;
    ov.z = *(unsigned*)&h2; ov.w = *(unsigned*)&h3;
    *(uint4*)(o + i) = ov;
}

__global__ void k_degree(const int* __restrict__ ei) {
    int e4 = (blockIdx.x * blockDim.x + threadIdx.x) * 4;
    if (e4 + 3 < N_EDGES) {
        int4 d = *(const int4*)(ei + N_EDGES + e4);
        if ((unsigned)d.x < N_NODES) atomicAdd(&g_cnt[d.x], 1);
        if ((unsigned)d.y < N_NODES) atomicAdd(&g_cnt[d.y], 1);
        if ((unsigned)d.z < N_NODES) atomicAdd(&g_cnt[d.z], 1);
        if ((unsigned)d.w < N_NODES) atomicAdd(&g_cnt[d.w], 1);
    }
}

__global__ __launch_bounds__(1024) void k_scan1() {
    __shared__ int warp_sums[32];
    int t = threadIdx.x, lane = t & 31, wid = t >> 5;
    int i0 = blockIdx.x * 4096 + t * 4;
    int v[4];
#pragma unroll
    for (int q = 0; q < 4; q++) {
        int i = i0 + q;
        v[q] = (i < N_NODES) ? g_cnt[i] : 0;
        if (i < N_NODES) g_dinv[i] = rsqrtf((float)v[q] + 1.0f);
    }
    int tsum = v[0] + v[1] + v[2] + v[3];
    int x = tsum;
#pragma unroll
    for (int s = 1; s < 32; s <<= 1) {
        int y = __shfl_up_sync(0xffffffffu, x, s);
        if (lane >= s) x += y;
    }
    if (lane == 31) warp_sums[wid] = x;
    __syncthreads();
    if (wid == 0) {
        int ws = warp_sums[lane];
        int xx = ws;
#pragma unroll
        for (int s = 1; s < 32; s <<= 1) {
            int y = __shfl_up_sync(0xffffffffu, xx, s);
            if (lane >= s) xx += y;
        }
        warp_sums[lane] = xx - ws;
    }
    __syncthreads();
    int run = warp_sums[wid] + (x - tsum);
#pragma unroll
    for (int q = 0; q < 4; q++) {
        int i = i0 + q;
        if (i < N_NODES) g_off[i] = run;
        run += v[q];
    }
    if (t == 1023) g_partial[blockIdx.x] = warp_sums[31] + x;
}

__global__ void k_scan3(int nblk) {
    __shared__ int sp[32];
    int t = threadIdx.x;
    if (t < 32) {
        int v = (t < nblk) ? g_partial[t] : 0;
        int x = v;
#pragma unroll
        for (int s = 1; s < 32; s <<= 1) {
            int y = __shfl_up_sync(0xffffffffu, x, s);
            if ((t & 31) >= s) x += y;
        }
        sp[t] = x - v;
    }
    __syncthreads();
    int i = blockIdx.x * blockDim.x + t;
    if (i < N_NODES) {
        int o = g_off[i] + sp[i >> 12];
        g_off[i] = o;
        g_cur[i] = o;
    }
}

__global__ void k_fill(const int* __restrict__ ei) {
    int e4 = (blockIdx.x * blockDim.x + threadIdx.x) * 4;
    if (e4 + 3 < N_EDGES) {
        int4 s = *(const int4*)(ei + e4);
        int4 d = *(const int4*)(ei + N_EDGES + e4);
        int ss[4] = {s.x, s.y, s.z, s.w};
        int dd[4] = {d.x, d.y, d.z, d.w};
#pragma unroll
        for (int q = 0; q < 4; q++) {
            if ((unsigned)ss[q] < N_NODES && (unsigned)dd[q] < N_NODES) {
                int pos = atomicAdd(&g_cur[dd[q]], 1);
                if ((unsigned)pos < N_EDGES) g_csr_i[pos] = ss[q];
            }
        }
    }
}

// ---------------- wmma GEMM: g_h16 = fp16( dinv[row] * (A @ W16[widx]) ) ------------
#define WLD 136
#define XLD 136
__global__ __launch_bounds__(256, 2) void k_gemm_w(const float* __restrict__ xin,
                                                   int a_sel, int widx) {
    __shared__ __align__(16) __half Ws[DIM * WLD];
    __shared__ __align__(16) __half Xs[DIM * XLD];
    int tid = threadIdx.x;
    int wid = tid >> 5, lane = tid & 31;
    int r0 = blockIdx.x * 128;

    {
        const uint4* src = (const uint4*)g_w16[widx];
#pragma unroll
        for (int it = 0; it < 8; it++) {
            int i = tid + it * 256;
            int row = i >> 4, col8 = (i & 15) << 3;
            *(uint4*)(Ws + row * WLD + col8) = src[i];
        }
    }

    if (a_sel == 0) {
        const float4* x4 = (const float4*)(xin + (size_t)r0 * DIM);
        bool full = (r0 + 128) <= N_NODES;
#pragma unroll
        for (int it = 0; it < 16; it++) {
            int j = tid + it * 256;
            int row = j >> 5, col4 = (j & 31) << 2;
            float4 v = make_float4(0.f, 0.f, 0.f, 0.f);
            if (full || (r0 + row) < N_NODES) v = x4[j];
            __half2 h0 = __floats2half2_rn(v.x, v.y);
            __half2 h1 = __floats2half2_rn(v.z, v.w);
            uint2 o;
            o.x = *(unsigned*)&h0; o.y = *(unsigned*)&h1;
            *(uint2*)(Xs + row * XLD + col4) = o;
        }
    } else {
        const uint4* src = (const uint4*)(g_h16b + (size_t)r0 * DIM);
#pragma unroll
        for (int it = 0; it < 8; it++) {
            int i = tid + it * 256;
            int row = i >> 4, col8 = (i & 15) << 3;
            *(uint4*)(Xs + row * XLD + col8) = src[i];
        }
    }
    __syncthreads();

    wmma::fragment<wmma::accumulator, 16, 16, 16, float> acc[8];
#pragma unroll
    for (int n = 0; n < 8; n++) wmma::fill_fragment(acc[n], 0.f);
#pragma unroll
    for (int k = 0; k < 8; k++) {
        wmma::fragment<wmma::matrix_a, 16, 16, 16, __half, wmma::row_major> af;
        wmma::load_matrix_sync(af, Xs + (wid * 16) * XLD + k * 16, XLD);
#pragma unroll
        for (int n = 0; n < 8; n++) {
            wmma::fragment<wmma::matrix_b, 16, 16, 16, __half, wmma::row_major> bf;
            wmma::load_matrix_sync(bf, Ws + (k * 16) * WLD + n * 16, WLD);
            wmma::mma_sync(acc[n], af, bf, acc[n]);
        }
    }
    __syncthreads();

    float* Cs = (float*)Ws + wid * 1024;
    int wr0 = r0 + wid * 16;
#pragma unroll
    for (int h = 0; h < 2; h++) {
#pragma unroll
        for (int n = 0; n < 4; n++)
            wmma::store_matrix_sync(Cs + n * 16, acc[h * 4 + n], 64, wmma::mem_row_major);
        __syncwarp();
        int r = lane >> 1;
        int cb = (lane & 1) * 32;
        int grow = wr0 + r;
        if (grow < N_NODES) {
            float dv = g_dinv[grow];
            const float* srcr = Cs + r * 64 + cb;
            __half* dstp = g_h16 + (size_t)grow * DIM + h * 64 + cb;
#pragma unroll
            for (int j = 0; j < 32; j += 8) {
                float4 v0 = *(const float4*)(srcr + j);
                float4 v1 = *(const float4*)(srcr + j + 4);
                __half2 h0 = __floats2half2_rn(v0.x * dv, v0.y * dv);
                __half2 h1 = __floats2half2_rn(v0.z * dv, v0.w * dv);
                __half2 h2 = __floats2half2_rn(v1.x * dv, v1.y * dv);
                __half2 h3 = __floats2half2_rn(v1.z * dv, v1.w * dv);
                uint4 o;
                o.x = *(unsigned*)&h0; o.y = *(unsigned*)&h1;
                o.z = *(unsigned*)&h2; o.w = *(unsigned*)&h3;
                *(uint4*)(dstp + j) = o;
            }
        }
        __syncwarp();
    }
}

// ---------------- edge aggregation: half-warp per edge, dual acc banks -------------
__device__ __forceinline__ void acc_row(float* acc, const uint4& r) {
    float2 f0 = __half22float2(*(__half2*)&r.x);
    float2 f1 = __half22float2(*(__half2*)&r.y);
    float2 f2 = __half22float2(*(__half2*)&r.z);
    float2 f3 = __half22float2(*(__half2*)&r.w);
    acc[0] += f0.x; acc[1] += f0.y; acc[2] += f1.x; acc[3] += f1.y;
    acc[4] += f2.x; acc[5] += f2.y; acc[6] += f3.x; acc[7] += f3.y;
}

// in_sel: 0=g_h16, 1=g_h16b. out_sel: 0=g_agg-style fp32? (unused now) 1=g_h16b, 2=g_h16.
__global__ __launch_bounds__(256) void k_agg(int in_sel, int out_sel, int out_scale,
                                             const float* __restrict__ bias) {
    int n = (blockIdx.x * blockDim.x + threadIdx.x) >> 5;
    int lane = threadIdx.x & 31;
    if (n >= N_NODES) return;
    int half = lane >> 4, hl = lane & 15;
    const uint4* in4 = (const uint4*)(in_sel ? g_h16b : g_h16);
    float dn = g_dinv[n];

    float acca[8], accb[8];
    {
        uint4 sv = __ldcg(&in4[(size_t)n * 16 + hl]);   // self (pre-scaled by dinv[n])
        float2 f0 = __half22float2(*(__half2*)&sv.x);
        float2 f1 = __half22float2(*(__half2*)&sv.y);
        float2 f2 = __half22float2(*(__half2*)&sv.z);
        float2 f3 = __half22float2(*(__half2*)&sv.w);
        float m = (half == 0) ? 1.f : 0.f;              // count self once
        acca[0] = m * f0.x; acca[1] = m * f0.y; acca[2] = m * f1.x; acca[3] = m * f1.y;
        acca[4] = m * f2.x; acca[5] = m * f2.y; acca[6] = m * f3.x; acca[7] = m * f3.y;
#pragma unroll
        for (int q = 0; q < 8; q++) accb[q] = 0.f;
    }

    int j = g_off[n];
    int end = j + g_cnt[n];
    for (; j + 16 <= end; j += 16) {
        int s0 = __ldcs(&g_csr_i[j + half]);
        int s1 = __ldcs(&g_csr_i[j + 2 + half]);
        int s2 = __ldcs(&g_csr_i[j + 4 + half]);
        int s3 = __ldcs(&g_csr_i[j + 6 + half]);
        int s4 = __ldcs(&g_csr_i[j + 8 + half]);
        int s5 = __ldcs(&g_csr_i[j + 10 + half]);
        int s6 = __ldcs(&g_csr_i[j + 12 + half]);
        int s7 = __ldcs(&g_csr_i[j + 14 + half]);
        uint4 r0 = __ldcg(&in4[(size_t)s0 * 16 + hl]);
        uint4 r1 = __ldcg(&in4[(size_t)s1 * 16 + hl]);
        uint4 r2 = __ldcg(&in4[(size_t)s2 * 16 + hl]);
        uint4 r3 = __ldcg(&in4[(size_t)s3 * 16 + hl]);
        uint4 r4 = __ldcg(&in4[(size_t)s4 * 16 + hl]);
        uint4 r5 = __ldcg(&in4[(size_t)s5 * 16 + hl]);
        uint4 r6 = __ldcg(&in4[(size_t)s6 * 16 + hl]);
        uint4 r7 = __ldcg(&in4[(size_t)s7 * 16 + hl]);
        acc_row(acca, r0); acc_row(accb, r1);
        acc_row(acca, r2); acc_row(accb, r3);
        acc_row(acca, r4); acc_row(accb, r5);
        acc_row(acca, r6); acc_row(accb, r7);
    }
    for (; j + 4 <= end; j += 4) {
        int s0 = __ldcs(&g_csr_i[j + half]);
        int s1 = __ldcs(&g_csr_i[j + 2 + half]);
        uint4 r0 = __ldcg(&in4[(size_t)s0 * 16 + hl]);
        uint4 r1 = __ldcg(&in4[(size_t)s1 * 16 + hl]);
        acc_row(acca, r0); acc_row(accb, r1);
    }
    for (; j + 2 <= end; j += 2) {
        int s = __ldcs(&g_csr_i[j + half]);
        uint4 r = __ldcg(&in4[(size_t)s * 16 + hl]);
        acc_row(acca, r);
    }
    if (j + half < end) {
        int s = __ldcs(&g_csr_i[j + half]);
        uint4 r = __ldcg(&in4[(size_t)s * 16 + hl]);
        acc_row(accb, r);
    }

    float acc[8];
#pragma unroll
    for (int q = 0; q < 8; q++) {
        float v = acca[q] + accb[q];
        acc[q] = v + __shfl_xor_sync(0xffffffffu, v, 16);
    }

    if (half == 0) {
#pragma unroll
        for (int q = 0; q < 8; q++) acc[q] *= dn;
        if (bias) {
            float4 b0 = *(const float4*)(bias + hl * 8);
            float4 b1 = *(const float4*)(bias + hl * 8 + 4);
            acc[0] = fmaxf(acc[0] + b0.x, 0.f); acc[1] = fmaxf(acc[1] + b0.y, 0.f);
            acc[2] = fmaxf(acc[2] + b0.z, 0.f); acc[3] = fmaxf(acc[3] + b0.w, 0.f);
            acc[4] = fmaxf(acc[4] + b1.x, 0.f); acc[5] = fmaxf(acc[5] + b1.y, 0.f);
            acc[6] = fmaxf(acc[6] + b1.z, 0.f); acc[7] = fmaxf(acc[7] + b1.w, 0.f);
        }
        if (out_scale) {
#pragma unroll
            for (int q = 0; q < 8; q++) acc[q] *= dn;
        }
        __half2 h0 = __floats2half2_rn(acc[0], acc[1]);
        __half2 h1 = __floats2half2_rn(acc[2], acc[3]);
        __half2 h2 = __floats2half2_rn(acc[4], acc[5]);
        __half2 h3 = __floats2half2_rn(acc[6], acc[7]);
        uint4 o;
        o.x = *(unsigned*)&h0; o.y = *(unsigned*)&h1;
        o.z = *(unsigned*)&h2; o.w = *(unsigned*)&h3;
        __half* outp = (out_sel == 1) ? g_h16b : g_h16;
        *(uint4*)(outp + (size_t)n * DIM + hl * 8) = o;
    }
}

// ---------------- readout: segmented sum of g_h16 (fp16) over sorted batch ids -----
#define NPB 256
__global__ void k_readout(const int* __restrict__ batch) {
    int d = threadIdx.x;
    int n0 = blockIdx.x * NPB;
    if (n0 >= N_NODES) return;
    int n1 = n0 + NPB;
    if (n1 > N_NODES) n1 = N_NODES;
    int curb = batch[n0];
    if ((unsigned)curb >= N_GRAPHS) curb = 0;
    float acc = 0.f;
    int c = 0;
    for (int n = n0; n < n1; n++) {
        int b = batch[n];
        if ((unsigned)b >= N_GRAPHS) b = 0;
        if (b != curb) {
            atomicAdd(&g_gsum[curb * DIM + d], acc);
            if (d == 0) atomicAdd(&g_gcnt[curb], (float)c);
            acc = 0.f; c = 0; curb = b;
        }
        acc += __half2float(g_h16[(size_t)n * DIM + d]);
        c++;
    }
    atomicAdd(&g_gsum[curb * DIM + d], acc);
    if (d == 0) atomicAdd(&g_gcnt[curb], (float)c);
}

// ---------------- final ----------------
__global__ __launch_bounds__(128) void k_final(const float* __restrict__ W3,
                                               const float* __restrict__ b3,
                                               float* __restrict__ out) {
    __shared__ float m[DIM];
    int g = blockIdx.x;
    int d = threadIdx.x;
    float c = g_gcnt[g];
    float inv = (c > 0.f) ? (1.f / c) : 0.f;
    m[d] = g_gsum[g * DIM + d] * inv;
    __syncthreads();
    float acc = 0.f;
#pragma unroll 8
    for (int k = 0; k < DIM; k++)
        acc = fmaf(m[k], W3[k * DIM + d], acc);
    out[g * DIM + d] = (c > 0.f) ? (acc + b3[d]) : 0.f;
}

// ---------------- launch ----------------
extern "C" void kernel_launch(void* const* d_in, const int* in_sizes, int n_in,
                              void* d_out, int out_size) {
    (void)in_sizes; (void)n_in; (void)out_size;
    const float* x     = (const float*)d_in[0];
    const int*   ei    = (const int*)d_in[1];
    const int*   batch = (const int*)d_in[2];
    const float* W1    = (const float*)d_in[3];
    const float* b1    = (const float*)d_in[4];
    const float* W2    = (const float*)d_in[5];
    const float* b2    = (const float*)d_in[6];
    const float* W3    = (const float*)d_in[7];
    const float* b3    = (const float*)d_in[8];
    float* out = (float*)d_out;

    int scan_blocks = (N_NODES + 4095) / 4096;
    int gemm_blocks = (N_NODES + 127) / 128;
    int agg_blocks = (N_NODES * 32 + 255) / 256;

    k_prepw<<<16, 256>>>(W1, W2);                                      // 1
    k_zero<<<(N_NODES + 255) / 256, 256>>>();                          // 2
    k_degree<<<(N_EDGES / 4 + 255) / 256, 256>>>(ei);                  // 3
    k_scan1<<<scan_blocks, 1024>>>();                                  // 4
    k_scan3<<<(N_NODES + 255) / 256, 256>>>(scan_blocks);              // 5
    k_gemm_w<<<gemm_blocks, 256>>>(x, 0, 0);                           // 6
    k_fill<<<(N_EDGES / 4 + 255) / 256, 256>>>(ei);                    // 7

    // layer 1: agg(g_h16) -> g_h16b = relu(dn*acc + b1)   (unscaled; feeds gemm2)
    k_agg<<<agg_blocks, 256>>>(0, 1, 0, b1);                           // 8
    // layer 2: gemm2 -> g_h16 (scaled) ; agg -> g_h16b = relu(dn*acc + b2) * dn
    k_gemm_w<<<gemm_blocks, 256>>>(x, 1, 1);                           // 9
    k_agg<<<agg_blocks, 256>>>(0, 1, 1, b2);                           // 10
    // layer 3: agg(g_h16b) -> g_h16 = fp16(dn*acc)
    k_agg<<<agg_blocks, 256>>>(1, 2, 0, nullptr);                      // 11

    k_readout<<<(N_NODES + NPB - 1) / NPB, 128>>>(batch);              // 12
    k_final<<<N_GRAPHS, 128>>>(W3, b3, out);                           // 13
}

// round 13
// speedup vs baseline: 1.4991x; 1.0248x over previous
#include <cuda_runtime.h>
#include <cuda_fp16.h>
#include <mma.h>
#include <cstdint>
#include <cstddef>

using namespace nvcuda;

#define N_NODES  100000
#define N_PAD    100096   // multiple of 128
#define N_EDGES  1600000
#define DIM      128
#define N_GRAPHS 512

// ---------------- scratch ----------------
__device__ __align__(16) __half g_h16[(size_t)N_NODES * DIM];   // gemm out / agg3 out
__device__ __align__(16) __half g_h16b[(size_t)N_PAD * DIM];    // agg1/agg2 out (gemm2 A)
__device__ __align__(16) __half g_w16[2][DIM * DIM];            // fp16 W1, W2 row-major
__device__ __align__(16) float  g_dinv[N_NODES];
__device__ __align__(16) int    g_cnt[N_NODES];
__device__ __align__(16) int    g_off[N_NODES];
__device__ __align__(16) int    g_cur[N_NODES];
__device__ __align__(16) int    g_csr_i[N_EDGES];               // src index only
__device__ __align__(16) float  g_gsum[N_GRAPHS * DIM];
__device__ __align__(16) float  g_gcnt[N_GRAPHS];
__device__ int g_partial[32];

// ---------------- setup ----------------
__global__ void k_zero() {
    int i = blockIdx.x * blockDim.x + threadIdx.x;
    if (i < N_NODES) g_cnt[i] = 0;
    if (i < N_GRAPHS * DIM) g_gsum[i] = 0.f;
    if (i < N_GRAPHS) g_gcnt[i] = 0.f;
}

__global__ __launch_bounds__(256) void k_prepw(const float* __restrict__ Wa,
                                               const float* __restrict__ Wb) {
    int w = blockIdx.x >> 3;
    const float* W = w ? Wb : Wa;
    __half* o = g_w16[w];
    int i = (blockIdx.x & 7) * 2048 + threadIdx.x * 8;
    float4 v0 = *(const float4*)(W + i);
    float4 v1 = *(const float4*)(W + i + 4);
    __half2 h0 = __floats2half2_rn(v0.x, v0.y);
    __half2 h1 = __floats2half2_rn(v0.z, v0.w);
    __half2 h2 = __floats2half2_rn(v1.x, v1.y);
    __half2 h3 = __floats2half2_rn(v1.z, v1.w);
    uint4 ov;
    ov.x = *(unsigned*)&h0; ov.y = *(unsigned*)&h1;
    ov.z = *(unsigned*)&h2; ov.w = *(unsigned*)&h3;
    *(uint4*)(o + i) = ov;
}

__global__ void k_degree(const int* __restrict__ ei) {
    int e4 = (blockIdx.x * blockDim.x + threadIdx.x) * 4;
    if (e4 + 3 < N_EDGES) {
        int4 d = *(const int4*)(ei + N_EDGES + e4);
        if ((unsigned)d.x < N_NODES) atomicAdd(&g_cnt[d.x], 1);
        if ((unsigned)d.y < N_NODES) atomicAdd(&g_cnt[d.y], 1);
        if ((unsigned)d.z < N_NODES) atomicAdd(&g_cnt[d.z], 1);
        if ((unsigned)d.w < N_NODES) atomicAdd(&g_cnt[d.w], 1);
    }
}

__global__ __launch_bounds__(1024) void k_scan1() {
    __shared__ int warp_sums[32];
    int t = threadIdx.x, lane = t & 31, wid = t >> 5;
    int i0 = blockIdx.x * 4096 + t * 4;
    int v[4];
#pragma unroll
    for (int q = 0; q < 4; q++) {
        int i = i0 + q;
        v[q] = (i < N_NODES) ? g_cnt[i] : 0;
        if (i < N_NODES) g_dinv[i] = rsqrtf((float)v[q] + 1.0f);
    }
    int tsum = v[0] + v[1] + v[2] + v[3];
    int x = tsum;
#pragma unroll
    for (int s = 1; s < 32; s <<= 1) {
        int y = __shfl_up_sync(0xffffffffu, x, s);
        if (lane >= s) x += y;
    }
    if (lane == 31) warp_sums[wid] = x;
    __syncthreads();
    if (wid == 0) {
        int ws = warp_sums[lane];
        int xx = ws;
#pragma unroll
        for (int s = 1; s < 32; s <<= 1) {
            int y = __shfl_up_sync(0xffffffffu, xx, s);
            if (lane >= s) xx += y;
        }
        warp_sums[lane] = xx - ws;
    }
    __syncthreads();
    int run = warp_sums[wid] + (x - tsum);
#pragma unroll
    for (int q = 0; q < 4; q++) {
        int i = i0 + q;
        if (i < N_NODES) g_off[i] = run;
        run += v[q];
    }
    if (t == 1023) g_partial[blockIdx.x] = warp_sums[31] + x;
}

__global__ void k_scan3(int nblk) {
    __shared__ int sp[32];
    int t = threadIdx.x;
    if (t < 32) {
        int v = (t < nblk) ? g_partial[t] : 0;
        int x = v;
#pragma unroll
        for (int s = 1; s < 32; s <<= 1) {
            int y = __shfl_up_sync(0xffffffffu, x, s);
            if ((t & 31) >= s) x += y;
        }
        sp[t] = x - v;
    }
    __syncthreads();
    int i = blockIdx.x * blockDim.x + t;
    if (i < N_NODES) {
        int o = g_off[i] + sp[i >> 12];
        g_off[i] = o;
        g_cur[i] = o;
    }
}

__global__ void k_fill(const int* __restrict__ ei) {
    int e4 = (blockIdx.x * blockDim.x + threadIdx.x) * 4;
    if (e4 + 3 < N_EDGES) {
        int4 s = *(const int4*)(ei + e4);
        int4 d = *(const int4*)(ei + N_EDGES + e4);
        int ss[4] = {s.x, s.y, s.z, s.w};
        int dd[4] = {d.x, d.y, d.z, d.w};
#pragma unroll
        for (int q = 0; q < 4; q++) {
            if ((unsigned)ss[q] < N_NODES && (unsigned)dd[q] < N_NODES) {
                int pos = atomicAdd(&g_cur[dd[q]], 1);
                if ((unsigned)pos < N_EDGES) g_csr_i[pos] = ss[q];
            }
        }
    }
}

// ---------------- wmma GEMM: g_h16 = fp16( dinv[row] * (A @ W16[widx]) ) ------------
#define WLD 136
#define XLD 136
__global__ __launch_bounds__(256, 2) void k_gemm_w(const float* __restrict__ xin,
                                                   int a_sel, int widx) {
    __shared__ __align__(16) __half Ws[DIM * WLD];
    __shared__ __align__(16) __half Xs[DIM * XLD];
    int tid = threadIdx.x;
    int wid = tid >> 5, lane = tid & 31;
    int r0 = blockIdx.x * 128;

    {
        const uint4* src = (const uint4*)g_w16[widx];
#pragma unroll
        for (int it = 0; it < 8; it++) {
            int i = tid + it * 256;
            int row = i >> 4, col8 = (i & 15) << 3;
            *(uint4*)(Ws + row * WLD + col8) = src[i];
        }
    }

    if (a_sel == 0) {
        const float4* x4 = (const float4*)(xin + (size_t)r0 * DIM);
        bool full = (r0 + 128) <= N_NODES;
#pragma unroll
        for (int it = 0; it < 16; it++) {
            int j = tid + it * 256;
            int row = j >> 5, col4 = (j & 31) << 2;
            float4 v = make_float4(0.f, 0.f, 0.f, 0.f);
            if (full || (r0 + row) < N_NODES) v = x4[j];
            __half2 h0 = __floats2half2_rn(v.x, v.y);
            __half2 h1 = __floats2half2_rn(v.z, v.w);
            uint2 o;
            o.x = *(unsigned*)&h0; o.y = *(unsigned*)&h1;
            *(uint2*)(Xs + row * XLD + col4) = o;
        }
    } else {
        const uint4* src = (const uint4*)(g_h16b + (size_t)r0 * DIM);
#pragma unroll
        for (int it = 0; it < 8; it++) {
            int i = tid + it * 256;
            int row = i >> 4, col8 = (i & 15) << 3;
            *(uint4*)(Xs + row * XLD + col8) = src[i];
        }
    }
    __syncthreads();

    wmma::fragment<wmma::accumulator, 16, 16, 16, float> acc[8];
#pragma unroll
    for (int n = 0; n < 8; n++) wmma::fill_fragment(acc[n], 0.f);
#pragma unroll
    for (int k = 0; k < 8; k++) {
        wmma::fragment<wmma::matrix_a, 16, 16, 16, __half, wmma::row_major> af;
        wmma::load_matrix_sync(af, Xs + (wid * 16) * XLD + k * 16, XLD);
#pragma unroll
        for (int n = 0; n < 8; n++) {
            wmma::fragment<wmma::matrix_b, 16, 16, 16, __half, wmma::row_major> bf;
            wmma::load_matrix_sync(bf, Ws + (k * 16) * WLD + n * 16, WLD);
            wmma::mma_sync(acc[n], af, bf, acc[n]);
        }
    }
    __syncthreads();

    float* Cs = (float*)Ws + wid * 1024;
    int wr0 = r0 + wid * 16;
#pragma unroll
    for (int h = 0; h < 2; h++) {
#pragma unroll
        for (int n = 0; n < 4; n++)
            wmma::store_matrix_sync(Cs + n * 16, acc[h * 4 + n], 64, wmma::mem_row_major);
        __syncwarp();
        int r = lane >> 1;
        int cb = (lane & 1) * 32;
        int grow = wr0 + r;
        if (grow < N_NODES) {
            float dv = g_dinv[grow];
            const float* srcr = Cs + r * 64 + cb;
            __half* dstp = g_h16 + (size_t)grow * DIM + h * 64 + cb;
#pragma unroll
            for (int j = 0; j < 32; j += 8) {
                float4 v0 = *(const float4*)(srcr + j);
                float4 v1 = *(const float4*)(srcr + j + 4);
                __half2 h0 = __floats2half2_rn(v0.x * dv, v0.y * dv);
                __half2 h1 = __floats2half2_rn(v0.z * dv, v0.w * dv);
                __half2 h2 = __floats2half2_rn(v1.x * dv, v1.y * dv);
                __half2 h3 = __floats2half2_rn(v1.z * dv, v1.w * dv);
                uint4 o;
                o.x = *(unsigned*)&h0; o.y = *(unsigned*)&h1;
                o.z = *(unsigned*)&h2; o.w = *(unsigned*)&h3;
                *(uint4*)(dstp + j) = o;
            }
        }
        __syncwarp();
    }
}

// ---------------- edge aggregation: half-warp per edge, dual acc banks -------------
__device__ __forceinline__ void acc_row(float* acc, const uint4& r) {
    float2 f0 = __half22float2(*(__half2*)&r.x);
    float2 f1 = __half22float2(*(__half2*)&r.y);
    float2 f2 = __half22float2(*(__half2*)&r.z);
    float2 f3 = __half22float2(*(__half2*)&r.w);
    acc[0] += f0.x; acc[1] += f0.y; acc[2] += f1.x; acc[3] += f1.y;
    acc[4] += f2.x; acc[5] += f2.y; acc[6] += f3.x; acc[7] += f3.y;
}

__global__ __launch_bounds__(256) void k_agg(int in_sel, int out_sel, int out_scale,
                                             const float* __restrict__ bias) {
    int n = (blockIdx.x * blockDim.x + threadIdx.x) >> 5;
    int lane = threadIdx.x & 31;
    if (n >= N_NODES) return;
    int half = lane >> 4, hl = lane & 15;
    const uint4* in4 = (const uint4*)(in_sel ? g_h16b : g_h16);
    float dn = g_dinv[n];

    float acca[8], accb[8];
    {
        uint4 sv = __ldcg(&in4[(size_t)n * 16 + hl]);
        float2 f0 = __half22float2(*(__half2*)&sv.x);
        float2 f1 = __half22float2(*(__half2*)&sv.y);
        float2 f2 = __half22float2(*(__half2*)&sv.z);
        float2 f3 = __half22float2(*(__half2*)&sv.w);
        float m = (half == 0) ? 1.f : 0.f;
        acca[0] = m * f0.x; acca[1] = m * f0.y; acca[2] = m * f1.x; acca[3] = m * f1.y;
        acca[4] = m * f2.x; acca[5] = m * f2.y; acca[6] = m * f3.x; acca[7] = m * f3.y;
#pragma unroll
        for (int q = 0; q < 8; q++) accb[q] = 0.f;
    }

    int j = g_off[n];
    int end = j + g_cnt[n];
    for (; j + 16 <= end; j += 16) {
        int s0 = __ldcs(&g_csr_i[j + half]);
        int s1 = __ldcs(&g_csr_i[j + 2 + half]);
        int s2 = __ldcs(&g_csr_i[j + 4 + half]);
        int s3 = __ldcs(&g_csr_i[j + 6 + half]);
        int s4 = __ldcs(&g_csr_i[j + 8 + half]);
        int s5 = __ldcs(&g_csr_i[j + 10 + half]);
        int s6 = __ldcs(&g_csr_i[j + 12 + half]);
        int s7 = __ldcs(&g_csr_i[j + 14 + half]);
        uint4 r0 = __ldcg(&in4[(size_t)s0 * 16 + hl]);
        uint4 r1 = __ldcg(&in4[(size_t)s1 * 16 + hl]);
        uint4 r2 = __ldcg(&in4[(size_t)s2 * 16 + hl]);
        uint4 r3 = __ldcg(&in4[(size_t)s3 * 16 + hl]);
        uint4 r4 = __ldcg(&in4[(size_t)s4 * 16 + hl]);
        uint4 r5 = __ldcg(&in4[(size_t)s5 * 16 + hl]);
        uint4 r6 = __ldcg(&in4[(size_t)s6 * 16 + hl]);
        uint4 r7 = __ldcg(&in4[(size_t)s7 * 16 + hl]);
        acc_row(acca, r0); acc_row(accb, r1);
        acc_row(acca, r2); acc_row(accb, r3);
        acc_row(acca, r4); acc_row(accb, r5);
        acc_row(acca, r6); acc_row(accb, r7);
    }
    for (; j + 4 <= end; j += 4) {
        int s0 = __ldcs(&g_csr_i[j + half]);
        int s1 = __ldcs(&g_csr_i[j + 2 + half]);
        uint4 r0 = __ldcg(&in4[(size_t)s0 * 16 + hl]);
        uint4 r1 = __ldcg(&in4[(size_t)s1 * 16 + hl]);
        acc_row(acca, r0); acc_row(accb, r1);
    }
    for (; j + 2 <= end; j += 2) {
        int s = __ldcs(&g_csr_i[j + half]);
        uint4 r = __ldcg(&in4[(size_t)s * 16 + hl]);
        acc_row(acca, r);
    }
    if (j + half < end) {
        int s = __ldcs(&g_csr_i[j + half]);
        uint4 r = __ldcg(&in4[(size_t)s * 16 + hl]);
        acc_row(accb, r);
    }

    float acc[8];
#pragma unroll
    for (int q = 0; q < 8; q++) {
        float v = acca[q] + accb[q];
        acc[q] = v + __shfl_xor_sync(0xffffffffu, v, 16);
    }

    if (half == 0) {
#pragma unroll
        for (int q = 0; q < 8; q++) acc[q] *= dn;
        if (bias) {
            float4 b0 = *(const float4*)(bias + hl * 8);
            float4 b1 = *(const float4*)(bias + hl * 8 + 4);
            acc[0] = fmaxf(acc[0] + b0.x, 0.f); acc[1] = fmaxf(acc[1] + b0.y, 0.f);
            acc[2] = fmaxf(acc[2] + b0.z, 0.f); acc[3] = fmaxf(acc[3] + b0.w, 0.f);
            acc[4] = fmaxf(acc[4] + b1.x, 0.f); acc[5] = fmaxf(acc[5] + b1.y, 0.f);
            acc[6] = fmaxf(acc[6] + b1.z, 0.f); acc[7] = fmaxf(acc[7] + b1.w, 0.f);
        }
        if (out_scale) {
#pragma unroll
            for (int q = 0; q < 8; q++) acc[q] *= dn;
        }
        __half2 h0 = __floats2half2_rn(acc[0], acc[1]);
        __half2 h1 = __floats2half2_rn(acc[2], acc[3]);
        __half2 h2 = __floats2half2_rn(acc[4], acc[5]);
        __half2 h3 = __floats2half2_rn(acc[6], acc[7]);
        uint4 o;
        o.x = *(unsigned*)&h0; o.y = *(unsigned*)&h1;
        o.z = *(unsigned*)&h2; o.w = *(unsigned*)&h3;
        __half* outp = (out_sel == 1) ? g_h16b : g_h16;
        *(uint4*)(outp + (size_t)n * DIM + hl * 8) = o;
    }
}

// ---------------- readout: segmented sum of g_h16 (fp16) over sorted batch ids -----
#define NPB 256
__global__ void k_readout(const int* __restrict__ batch) {
    int d = threadIdx.x;
    int n0 = blockIdx.x * NPB;
    if (n0 >= N_NODES) return;
    int n1 = n0 + NPB;
    if (n1 > N_NODES) n1 = N_NODES;
    int curb = batch[n0];
    if ((unsigned)curb >= N_GRAPHS) curb = 0;
    float acc = 0.f;
    int c = 0;
    for (int n = n0; n < n1; n++) {
        int b = batch[n];
        if ((unsigned)b >= N_GRAPHS) b = 0;
        if (b != curb) {
            atomicAdd(&g_gsum[curb * DIM + d], acc);
            if (d == 0) atomicAdd(&g_gcnt[curb], (float)c);
            acc = 0.f; c = 0; curb = b;
        }
        acc += __half2float(g_h16[(size_t)n * DIM + d]);
        c++;
    }
    atomicAdd(&g_gsum[curb * DIM + d], acc);
    if (d == 0) atomicAdd(&g_gcnt[curb], (float)c);
}

// ---------------- final ----------------
__global__ __launch_bounds__(128) void k_final(const float* __restrict__ W3,
                                               const float* __restrict__ b3,
                                               float* __restrict__ out) {
    __shared__ float m[DIM];
    int g = blockIdx.x;
    int d = threadIdx.x;
    float c = g_gcnt[g];
    float inv = (c > 0.f) ? (1.f / c) : 0.f;
    m[d] = g_gsum[g * DIM + d] * inv;
    __syncthreads();
    float acc = 0.f;
#pragma unroll 8
    for (int k = 0; k < DIM; k++)
        acc = fmaf(m[k], W3[k * DIM + d], acc);
    out[g * DIM + d] = (c > 0.f) ? (acc + b3[d]) : 0.f;
}

// ---------------- launch: fork gemm1 onto a side stream -----------------
extern "C" void kernel_launch(void* const* d_in, const int* in_sizes, int n_in,
                              void* d_out, int out_size) {
    (void)in_sizes; (void)n_in; (void)out_size;
    const float* x     = (const float*)d_in[0];
    const int*   ei    = (const int*)d_in[1];
    const int*   batch = (const int*)d_in[2];
    const float* W1    = (const float*)d_in[3];
    const float* b1    = (const float*)d_in[4];
    const float* W2    = (const float*)d_in[5];
    const float* b2    = (const float*)d_in[6];
    const float* W3    = (const float*)d_in[7];
    const float* b3    = (const float*)d_in[8];
    float* out = (float*)d_out;

    int scan_blocks = (N_NODES + 4095) / 4096;
    int gemm_blocks = (N_NODES + 127) / 128;
    int agg_blocks = (N_NODES * 32 + 255) / 256;

    cudaStream_t s2;
    cudaStreamCreateWithFlags(&s2, cudaStreamNonBlocking);
    cudaEvent_t ev_fork, ev_dinv, ev_gemm1;
    cudaEventCreateWithFlags(&ev_fork, cudaEventDisableTiming);
    cudaEventCreateWithFlags(&ev_dinv, cudaEventDisableTiming);
    cudaEventCreateWithFlags(&ev_gemm1, cudaEventDisableTiming);

    // fork: prepw runs on s2 concurrently with zero/degree
    cudaEventRecord(ev_fork, 0);
    cudaStreamWaitEvent(s2, ev_fork, 0);
    k_prepw<<<16, 256, 0, s2>>>(W1, W2);

    // main: CSR setup chain
    k_zero<<<(N_NODES + 255) / 256, 256>>>();
    k_degree<<<(N_EDGES / 4 + 255) / 256, 256>>>(ei);
    k_scan1<<<scan_blocks, 1024>>>();
    cudaEventRecord(ev_dinv, 0);

    // s2: gemm1 (needs prepw + dinv)
    cudaStreamWaitEvent(s2, ev_dinv, 0);
    k_gemm_w<<<gemm_blocks, 256, 0, s2>>>(x, 0, 0);
    cudaEventRecord(ev_gemm1, s2);

    // main continues CSR build concurrently with gemm1
    k_scan3<<<(N_NODES + 255) / 256, 256>>>(scan_blocks);
    k_fill<<<(N_EDGES / 4 + 255) / 256, 256>>>(ei);

    // join: agg1 needs gemm1 (g_h16) + fill (CSR)
    cudaStreamWaitEvent(0, ev_gemm1, 0);

    // layer 1: agg(g_h16) -> g_h16b = relu(dn*acc + b1)
    k_agg<<<agg_blocks, 256>>>(0, 1, 0, b1);
    // layer 2: gemm2 -> g_h16 (scaled) ; agg -> g_h16b = relu(dn*acc + b2) * dn
    k_gemm_w<<<gemm_blocks, 256>>>(x, 1, 1);
    k_agg<<<agg_blocks, 256>>>(0, 1, 1, b2);
    // layer 3: agg(g_h16b) -> g_h16 = fp16(dn*acc)
    k_agg<<<agg_blocks, 256>>>(1, 2, 0, nullptr);

    k_readout<<<(N_NODES + NPB - 1) / NPB, 128>>>(batch);
    k_final<<<N_GRAPHS, 128>>>(W3, b3, out);
}

// round 14
// speedup vs baseline: 1.5080x; 1.0059x over previous
#include <cuda_runtime.h>
#include <cuda_fp16.h>
#include <mma.h>
#include <cstdint>
#include <cstddef>

using namespace nvcuda;

#define N_NODES  100000
#define N_PAD    100096   // multiple of 128
#define N_EDGES  1600000
#define DIM      128
#define N_GRAPHS 512

// ---------------- scratch ----------------
__device__ __align__(16) __half g_h16[(size_t)N_NODES * DIM];   // gemm out / agg3 out
__device__ __align__(16) __half g_h16b[(size_t)N_PAD * DIM];    // agg1/agg2 out (gemm2 A)
__device__ __align__(16) __half g_w16[2][DIM * DIM];            // fp16 W1, W2 row-major
__device__ __align__(16) float  g_dinv[N_NODES];
__device__ __align__(16) int    g_cnt[N_NODES];
__device__ __align__(16) int    g_off[N_NODES];
__device__ __align__(16) int    g_cur[N_NODES];
__device__ __align__(16) int    g_csr_i[N_EDGES];               // src index only
__device__ __align__(16) float  g_gsum[N_GRAPHS * DIM];
__device__ __align__(16) float  g_gcnt[N_GRAPHS];
__device__ int g_partial[32];

// ---------------- setup ----------------
__global__ void k_zero() {
    int i = blockIdx.x * blockDim.x + threadIdx.x;
    if (i < N_NODES) g_cnt[i] = 0;
    if (i < N_GRAPHS * DIM) g_gsum[i] = 0.f;
    if (i < N_GRAPHS) g_gcnt[i] = 0.f;
}

__global__ __launch_bounds__(256) void k_prepw(const float* __restrict__ Wa,
                                               const float* __restrict__ Wb) {
    int w = blockIdx.x >> 3;
    const float* W = w ? Wb : Wa;
    __half* o = g_w16[w];
    int i = (blockIdx.x & 7) * 2048 + threadIdx.x * 8;
    float4 v0 = *(const float4*)(W + i);
    float4 v1 = *(const float4*)(W + i + 4);
    __half2 h0 = __floats2half2_rn(v0.x, v0.y);
    __half2 h1 = __floats2half2_rn(v0.z, v0.w);
    __half2 h2 = __floats2half2_rn(v1.x, v1.y);
    __half2 h3 = __floats2half2_rn(v1.z, v1.w);
    uint4 ov;
    ov.x = *(unsigned*)&h0; ov.y = *(unsigned*)&h1;
    ov.z = *(unsigned*)&h2; ov.w = *(unsigned*)&h3;
    *(uint4*)(o + i) = ov;
}

__global__ void k_degree(const int* __restrict__ ei) {
    int e4 = (blockIdx.x * blockDim.x + threadIdx.x) * 4;
    if (e4 + 3 < N_EDGES) {
        int4 d = *(const int4*)(ei + N_EDGES + e4);
        if ((unsigned)d.x < N_NODES) atomicAdd(&g_cnt[d.x], 1);
        if ((unsigned)d.y < N_NODES) atomicAdd(&g_cnt[d.y], 1);
        if ((unsigned)d.z < N_NODES) atomicAdd(&g_cnt[d.z], 1);
        if ((unsigned)d.w < N_NODES) atomicAdd(&g_cnt[d.w], 1);
    }
}

__global__ __launch_bounds__(1024) void k_scan1() {
    __shared__ int warp_sums[32];
    int t = threadIdx.x, lane = t & 31, wid = t >> 5;
    int i0 = blockIdx.x * 4096 + t * 4;
    int v[4];
#pragma unroll
    for (int q = 0; q < 4; q++) {
        int i = i0 + q;
        v[q] = (i < N_NODES) ? g_cnt[i] : 0;
        if (i < N_NODES) g_dinv[i] = rsqrtf((float)v[q] + 1.0f);
    }
    int tsum = v[0] + v[1] + v[2] + v[3];
    int x = tsum;
#pragma unroll
    for (int s = 1; s < 32; s <<= 1) {
        int y = __shfl_up_sync(0xffffffffu, x, s);
        if (lane >= s) x += y;
    }
    if (lane == 31) warp_sums[wid] = x;
    __syncthreads();
    if (wid == 0) {
        int ws = warp_sums[lane];
        int xx = ws;
#pragma unroll
        for (int s = 1; s < 32; s <<= 1) {
            int y = __shfl_up_sync(0xffffffffu, xx, s);
            if (lane >= s) xx += y;
        }
        warp_sums[lane] = xx - ws;
    }
    __syncthreads();
    int run = warp_sums[wid] + (x - tsum);
#pragma unroll
    for (int q = 0; q < 4; q++) {
        int i = i0 + q;
        if (i < N_NODES) g_off[i] = run;
        run += v[q];
    }
    if (t == 1023) g_partial[blockIdx.x] = warp_sums[31] + x;
}

__global__ void k_scan3(int nblk) {
    __shared__ int sp[32];
    int t = threadIdx.x;
    if (t < 32) {
        int v = (t < nblk) ? g_partial[t] : 0;
        int x = v;
#pragma unroll
        for (int s = 1; s < 32; s <<= 1) {
            int y = __shfl_up_sync(0xffffffffu, x, s);
            if ((t & 31) >= s) x += y;
        }
        sp[t] = x - v;
    }
    __syncthreads();
    int i = blockIdx.x * blockDim.x + t;
    if (i < N_NODES) {
        int o = g_off[i] + sp[i >> 12];
        g_off[i] = o;
        g_cur[i] = o;
    }
}

__global__ void k_fill(const int* __restrict__ ei) {
    int e4 = (blockIdx.x * blockDim.x + threadIdx.x) * 4;
    if (e4 + 3 < N_EDGES) {
        int4 s = *(const int4*)(ei + e4);
        int4 d = *(const int4*)(ei + N_EDGES + e4);
        int ss[4] = {s.x, s.y, s.z, s.w};
        int dd[4] = {d.x, d.y, d.z, d.w};
#pragma unroll
        for (int q = 0; q < 4; q++) {
            if ((unsigned)ss[q] < N_NODES && (unsigned)dd[q] < N_NODES) {
                int pos = atomicAdd(&g_cur[dd[q]], 1);
                if ((unsigned)pos < N_EDGES) g_csr_i[pos] = ss[q];
            }
        }
    }
}

// ---------------- wmma GEMM: g_h16 = fp16( dinv[row] * (A @ W16[widx]) ) ------------
// 8 warps in a 4M x 2N grid: each warp 32 rows x 64 cols (2 m-frags x 4 n-frags).
// Fragment LDS traffic: 8k*(2+4)=48 loads/warp vs 72 in the 1Mx8N layout.
#define WLD 136
#define XLD 136
__global__ __launch_bounds__(256, 2) void k_gemm_w(const float* __restrict__ xin,
                                                   int a_sel, int widx) {
    __shared__ __align__(16) __half Ws[DIM * WLD];   // also C staging in epilogue
    __shared__ __align__(16) __half Xs[DIM * XLD];
    int tid = threadIdx.x;
    int wid = tid >> 5, lane = tid & 31;
    int wm = wid & 3;        // 0..3 -> rows wm*32
    int wn = wid >> 2;       // 0..1 -> cols wn*64
    int r0 = blockIdx.x * 128;

    {
        const uint4* src = (const uint4*)g_w16[widx];
#pragma unroll
        for (int it = 0; it < 8; it++) {
            int i = tid + it * 256;
            int row = i >> 4, col8 = (i & 15) << 3;
            *(uint4*)(Ws + row * WLD + col8) = src[i];
        }
    }

    if (a_sel == 0) {
        const float4* x4 = (const float4*)(xin + (size_t)r0 * DIM);
        bool full = (r0 + 128) <= N_NODES;
#pragma unroll
        for (int it = 0; it < 16; it++) {
            int j = tid + it * 256;
            int row = j >> 5, col4 = (j & 31) << 2;
            float4 v = make_float4(0.f, 0.f, 0.f, 0.f);
            if (full || (r0 + row) < N_NODES) v = x4[j];
            __half2 h0 = __floats2half2_rn(v.x, v.y);
            __half2 h1 = __floats2half2_rn(v.z, v.w);
            uint2 o;
            o.x = *(unsigned*)&h0; o.y = *(unsigned*)&h1;
            *(uint2*)(Xs + row * XLD + col4) = o;
        }
    } else {
        const uint4* src = (const uint4*)(g_h16b + (size_t)r0 * DIM);
#pragma unroll
        for (int it = 0; it < 8; it++) {
            int i = tid + it * 256;
            int row = i >> 4, col8 = (i & 15) << 3;
            *(uint4*)(Xs + row * XLD + col8) = src[i];
        }
    }
    __syncthreads();

    wmma::fragment<wmma::accumulator, 16, 16, 16, float> acc[2][4];
#pragma unroll
    for (int mi = 0; mi < 2; mi++)
#pragma unroll
        for (int ni = 0; ni < 4; ni++) wmma::fill_fragment(acc[mi][ni], 0.f);

#pragma unroll
    for (int k = 0; k < 8; k++) {
        wmma::fragment<wmma::matrix_a, 16, 16, 16, __half, wmma::row_major> af[2];
#pragma unroll
        for (int mi = 0; mi < 2; mi++)
            wmma::load_matrix_sync(af[mi], Xs + (wm * 32 + mi * 16) * XLD + k * 16, XLD);
#pragma unroll
        for (int ni = 0; ni < 4; ni++) {
            wmma::fragment<wmma::matrix_b, 16, 16, 16, __half, wmma::row_major> bf;
            wmma::load_matrix_sync(bf, Ws + (k * 16) * WLD + wn * 64 + ni * 16, WLD);
#pragma unroll
            for (int mi = 0; mi < 2; mi++)
                wmma::mma_sync(acc[mi][ni], af[mi], bf, acc[mi][ni]);
        }
    }
    __syncthreads();  // done reading Ws; reuse as C staging (8 warps x 4KB = 32KB)

    float* Cs = (float*)Ws + wid * 1024;  // 16 x 64 f32 per warp
#pragma unroll
    for (int mi = 0; mi < 2; mi++) {
#pragma unroll
        for (int ni = 0; ni < 4; ni++)
            wmma::store_matrix_sync(Cs + ni * 16, acc[mi][ni], 64, wmma::mem_row_major);
        __syncwarp();
        int r = lane >> 1;                 // 0..15
        int cb = (lane & 1) * 32;          // 0 or 32 within the warp's 64 cols
        int grow = r0 + wm * 32 + mi * 16 + r;
        if (grow < N_NODES) {
            float dv = g_dinv[grow];
            const float* srcr = Cs + r * 64 + cb;
            __half* dstp = g_h16 + (size_t)grow * DIM + wn * 64 + cb;
#pragma unroll
            for (int j = 0; j < 32; j += 8) {
                float4 v0 = *(const float4*)(srcr + j);
                float4 v1 = *(const float4*)(srcr + j + 4);
                __half2 h0 = __floats2half2_rn(v0.x * dv, v0.y * dv);
                __half2 h1 = __floats2half2_rn(v0.z * dv, v0.w * dv);
                __half2 h2 = __floats2half2_rn(v1.x * dv, v1.y * dv);
                __half2 h3 = __floats2half2_rn(v1.z * dv, v1.w * dv);
                uint4 o;
                o.x = *(unsigned*)&h0; o.y = *(unsigned*)&h1;
                o.z = *(unsigned*)&h2; o.w = *(unsigned*)&h3;
                *(uint4*)(dstp + j) = o;
            }
        }
        __syncwarp();
    }
}

// ---------------- edge aggregation: half-warp per edge, dual acc banks -------------
__device__ __forceinline__ void acc_row(float* acc, const uint4& r) {
    float2 f0 = __half22float2(*(__half2*)&r.x);
    float2 f1 = __half22float2(*(__half2*)&r.y);
    float2 f2 = __half22float2(*(__half2*)&r.z);
    float2 f3 = __half22float2(*(__half2*)&r.w);
    acc[0] += f0.x; acc[1] += f0.y; acc[2] += f1.x; acc[3] += f1.y;
    acc[4] += f2.x; acc[5] += f2.y; acc[6] += f3.x; acc[7] += f3.y;
}

__global__ __launch_bounds__(256) void k_agg(int in_sel, int out_sel, int out_scale,
                                             const float* __restrict__ bias) {
    int n = (blockIdx.x * blockDim.x + threadIdx.x) >> 5;
    int lane = threadIdx.x & 31;
    if (n >= N_NODES) return;
    int half = lane >> 4, hl = lane & 15;
    const uint4* in4 = (const uint4*)(in_sel ? g_h16b : g_h16);
    float dn = g_dinv[n];

    float acca[8], accb[8];
    {
        uint4 sv = __ldcg(&in4[(size_t)n * 16 + hl]);
        float2 f0 = __half22float2(*(__half2*)&sv.x);
        float2 f1 = __half22float2(*(__half2*)&sv.y);
        float2 f2 = __half22float2(*(__half2*)&sv.z);
        float2 f3 = __half22float2(*(__half2*)&sv.w);
        float m = (half == 0) ? 1.f : 0.f;
        acca[0] = m * f0.x; acca[1] = m * f0.y; acca[2] = m * f1.x; acca[3] = m * f1.y;
        acca[4] = m * f2.x; acca[5] = m * f2.y; acca[6] = m * f3.x; acca[7] = m * f3.y;
#pragma unroll
        for (int q = 0; q < 8; q++) accb[q] = 0.f;
    }

    int j = g_off[n];
    int end = j + g_cnt[n];
    for (; j + 16 <= end; j += 16) {
        int s0 = __ldcs(&g_csr_i[j + half]);
        int s1 = __ldcs(&g_csr_i[j + 2 + half]);
        int s2 = __ldcs(&g_csr_i[j + 4 + half]);
        int s3 = __ldcs(&g_csr_i[j + 6 + half]);
        int s4 = __ldcs(&g_csr_i[j + 8 + half]);
        int s5 = __ldcs(&g_csr_i[j + 10 + half]);
        int s6 = __ldcs(&g_csr_i[j + 12 + half]);
        int s7 = __ldcs(&g_csr_i[j + 14 + half]);
        uint4 r0 = __ldcg(&in4[(size_t)s0 * 16 + hl]);
        uint4 r1 = __ldcg(&in4[(size_t)s1 * 16 + hl]);
        uint4 r2 = __ldcg(&in4[(size_t)s2 * 16 + hl]);
        uint4 r3 = __ldcg(&in4[(size_t)s3 * 16 + hl]);
        uint4 r4 = __ldcg(&in4[(size_t)s4 * 16 + hl]);
        uint4 r5 = __ldcg(&in4[(size_t)s5 * 16 + hl]);
        uint4 r6 = __ldcg(&in4[(size_t)s6 * 16 + hl]);
        uint4 r7 = __ldcg(&in4[(size_t)s7 * 16 + hl]);
        acc_row(acca, r0); acc_row(accb, r1);
        acc_row(acca, r2); acc_row(accb, r3);
        acc_row(acca, r4); acc_row(accb, r5);
        acc_row(acca, r6); acc_row(accb, r7);
    }
    for (; j + 4 <= end; j += 4) {
        int s0 = __ldcs(&g_csr_i[j + half]);
        int s1 = __ldcs(&g_csr_i[j + 2 + half]);
        uint4 r0 = __ldcg(&in4[(size_t)s0 * 16 + hl]);
        uint4 r1 = __ldcg(&in4[(size_t)s1 * 16 + hl]);
        acc_row(acca, r0); acc_row(accb, r1);
    }
    for (; j + 2 <= end; j += 2) {
        int s = __ldcs(&g_csr_i[j + half]);
        uint4 r = __ldcg(&in4[(size_t)s * 16 + hl]);
        acc_row(acca, r);
    }
    if (j + half < end) {
        int s = __ldcs(&g_csr_i[j + half]);
        uint4 r = __ldcg(&in4[(size_t)s * 16 + hl]);
        acc_row(accb, r);
    }

    float acc[8];
#pragma unroll
    for (int q = 0; q < 8; q++) {
        float v = acca[q] + accb[q];
        acc[q] = v + __shfl_xor_sync(0xffffffffu, v, 16);
    }

    if (half == 0) {
#pragma unroll
        for (int q = 0; q < 8; q++) acc[q] *= dn;
        if (bias) {
            float4 b0 = *(const float4*)(bias + hl * 8);
            float4 b1 = *(const float4*)(bias + hl * 8 + 4);
            acc[0] = fmaxf(acc[0] + b0.x, 0.f); acc[1] = fmaxf(acc[1] + b0.y, 0.f);
            acc[2] = fmaxf(acc[2] + b0.z, 0.f); acc[3] = fmaxf(acc[3] + b0.w, 0.f);
            acc[4] = fmaxf(acc[4] + b1.x, 0.f); acc[5] = fmaxf(acc[5] + b1.y, 0.f);
            acc[6] = fmaxf(acc[6] + b1.z, 0.f); acc[7] = fmaxf(acc[7] + b1.w, 0.f);
        }
        if (out_scale) {
#pragma unroll
            for (int q = 0; q < 8; q++) acc[q] *= dn;
        }
        __half2 h0 = __floats2half2_rn(acc[0], acc[1]);
        __half2 h1 = __floats2half2_rn(acc[2], acc[3]);
        __half2 h2 = __floats2half2_rn(acc[4], acc[5]);
        __half2 h3 = __floats2half2_rn(acc[6], acc[7]);
        uint4 o;
        o.x = *(unsigned*)&h0; o.y = *(unsigned*)&h1;
        o.z = *(unsigned*)&h2; o.w = *(unsigned*)&h3;
        __half* outp = (out_sel == 1) ? g_h16b : g_h16;
        *(uint4*)(outp + (size_t)n * DIM + hl * 8) = o;
    }
}

// ---------------- readout: segmented sum of g_h16 (fp16) over sorted batch ids -----
#define NPB 256
__global__ void k_readout(const int* __restrict__ batch) {
    int d = threadIdx.x;
    int n0 = blockIdx.x * NPB;
    if (n0 >= N_NODES) return;
    int n1 = n0 + NPB;
    if (n1 > N_NODES) n1 = N_NODES;
    int curb = batch[n0];
    if ((unsigned)curb >= N_GRAPHS) curb = 0;
    float acc = 0.f;
    int c = 0;
    for (int n = n0; n < n1; n++) {
        int b = batch[n];
        if ((unsigned)b >= N_GRAPHS) b = 0;
        if (b != curb) {
            atomicAdd(&g_gsum[curb * DIM + d], acc);
            if (d == 0) atomicAdd(&g_gcnt[curb], (float)c);
            acc = 0.f; c = 0; curb = b;
        }
        acc += __half2float(g_h16[(size_t)n * DIM + d]);
        c++;
    }
    atomicAdd(&g_gsum[curb * DIM + d], acc);
    if (d == 0) atomicAdd(&g_gcnt[curb], (float)c);
}

// ---------------- final ----------------
__global__ __launch_bounds__(128) void k_final(const float* __restrict__ W3,
                                               const float* __restrict__ b3,
                                               float* __restrict__ out) {
    __shared__ float m[DIM];
    int g = blockIdx.x;
    int d = threadIdx.x;
    float c = g_gcnt[g];
    float inv = (c > 0.f) ? (1.f / c) : 0.f;
    m[d] = g_gsum[g * DIM + d] * inv;
    __syncthreads();
    float acc = 0.f;
#pragma unroll 8
    for (int k = 0; k < DIM; k++)
        acc = fmaf(m[k], W3[k * DIM + d], acc);
    out[g * DIM + d] = (c > 0.f) ? (acc + b3[d]) : 0.f;
}

// ---------------- launch: fork gemm1 onto a side stream -----------------
extern "C" void kernel_launch(void* const* d_in, const int* in_sizes, int n_in,
                              void* d_out, int out_size) {
    (void)in_sizes; (void)n_in; (void)out_size;
    const float* x     = (const float*)d_in[0];
    const int*   ei    = (const int*)d_in[1];
    const int*   batch = (const int*)d_in[2];
    const float* W1    = (const float*)d_in[3];
    const float* b1    = (const float*)d_in[4];
    const float* W2    = (const float*)d_in[5];
    const float* b2    = (const float*)d_in[6];
    const float* W3    = (const float*)d_in[7];
    const float* b3    = (const float*)d_in[8];
    float* out = (float*)d_out;

    int scan_blocks = (N_NODES + 4095) / 4096;
    int gemm_blocks = (N_NODES + 127) / 128;
    int agg_blocks = (N_NODES * 32 + 255) / 256;

    cudaStream_t s2;
    cudaStreamCreateWithFlags(&s2, cudaStreamNonBlocking);
    cudaEvent_t ev_fork, ev_dinv, ev_gemm1;
    cudaEventCreateWithFlags(&ev_fork, cudaEventDisableTiming);
    cudaEventCreateWithFlags(&ev_dinv, cudaEventDisableTiming);
    cudaEventCreateWithFlags(&ev_gemm1, cudaEventDisableTiming);

    // fork: prepw runs on s2 concurrently with zero/degree
    cudaEventRecord(ev_fork, 0);
    cudaStreamWaitEvent(s2, ev_fork, 0);
    k_prepw<<<16, 256, 0, s2>>>(W1, W2);

    // main: CSR setup chain
    k_zero<<<(N_NODES + 255) / 256, 256>>>();
    k_degree<<<(N_EDGES / 4 + 255) / 256, 256>>>(ei);
    k_scan1<<<scan_blocks, 1024>>>();
    cudaEventRecord(ev_dinv, 0);

    // s2: gemm1 (needs prepw + dinv)
    cudaStreamWaitEvent(s2, ev_dinv, 0);
    k_gemm_w<<<gemm_blocks, 256, 0, s2>>>(x, 0, 0);
    cudaEventRecord(ev_gemm1, s2);

    // main continues CSR build concurrently with gemm1
    k_scan3<<<(N_NODES + 255) / 256, 256>>>(scan_blocks);
    k_fill<<<(N_EDGES / 4 + 255) / 256, 256>>>(ei);

    // join: agg1 needs gemm1 (g_h16) + fill (CSR)
    cudaStreamWaitEvent(0, ev_gemm1, 0);

    // layer 1: agg(g_h16) -> g_h16b = relu(dn*acc + b1)
    k_agg<<<agg_blocks, 256>>>(0, 1, 0, b1);
    // layer 2: gemm2 -> g_h16 (scaled) ; agg -> g_h16b = relu(dn*acc + b2) * dn
    k_gemm_w<<<gemm_blocks, 256>>>(x, 1, 1);
    k_agg<<<agg_blocks, 256>>>(0, 1, 1, b2);
    // layer 3: agg(g_h16b) -> g_h16 = fp16(dn*acc)
    k_agg<<<agg_blocks, 256>>>(1, 2, 0, nullptr);

    k_readout<<<(N_NODES + NPB - 1) / NPB, 128>>>(batch);
    k_final<<<N_GRAPHS, 128>>>(W3, b3, out);
}

// round 15
// speedup vs baseline: 1.8642x; 1.2363x over previous
#include <cuda_runtime.h>
#include <cuda_fp16.h>
#include <mma.h>
#include <cstdint>
#include <cstddef>

using namespace nvcuda;

#define N_NODES  100000
#define N_PAD    100096   // multiple of 128
#define N_EDGES  1600000
#define DIM      128
#define N_GRAPHS 512

// ---------------- scratch ----------------
__device__ __align__(16) __half g_h16[(size_t)N_NODES * DIM];   // gemm out (gather src)
__device__ __align__(16) __half g_h16b[(size_t)N_PAD * DIM];    // agg1/agg2 out (gemm2 A)
__device__ __align__(16) __half g_w16[2][DIM * DIM];            // fp16 W1, W2 row-major
__device__ __align__(16) float  g_dinv[N_NODES];
__device__ __align__(16) int    g_cnt[N_NODES];
__device__ __align__(16) int    g_off[N_NODES];                 // after fill: segment END
__device__ __align__(16) int    g_csr_i[N_EDGES];               // src index only
__device__ __align__(16) float  g_gsum[N_GRAPHS * DIM];
__device__ __align__(16) float  g_gcnt[N_GRAPHS];
__device__ int g_partial[32];

// ---------------- setup ----------------
__global__ void k_zero() {
    int i = blockIdx.x * blockDim.x + threadIdx.x;
    if (i < N_NODES) g_cnt[i] = 0;
    if (i < N_GRAPHS * DIM) g_gsum[i] = 0.f;
    if (i < N_GRAPHS) g_gcnt[i] = 0.f;
}

__global__ __launch_bounds__(256) void k_prepw(const float* __restrict__ Wa,
                                               const float* __restrict__ Wb) {
    int w = blockIdx.x >> 3;
    const float* W = w ? Wb : Wa;
    __half* o = g_w16[w];
    int i = (blockIdx.x & 7) * 2048 + threadIdx.x * 8;
    float4 v0 = *(const float4*)(W + i);
    float4 v1 = *(const float4*)(W + i + 4);
    __half2 h0 = __floats2half2_rn(v0.x, v0.y);
    __half2 h1 = __floats2half2_rn(v0.z, v0.w);
    __half2 h2 = __floats2half2_rn(v1.x, v1.y);
    __half2 h3 = __floats2half2_rn(v1.z, v1.w);
    uint4 ov;
    ov.x = *(unsigned*)&h0; ov.y = *(unsigned*)&h1;
    ov.z = *(unsigned*)&h2; ov.w = *(unsigned*)&h3;
    *(uint4*)(o + i) = ov;
}

__global__ void k_degree(const int* __restrict__ ei) {
    int e4 = (blockIdx.x * blockDim.x + threadIdx.x) * 4;
    if (e4 + 3 < N_EDGES) {
        int4 d = *(const int4*)(ei + N_EDGES + e4);
        if ((unsigned)d.x < N_NODES) atomicAdd(&g_cnt[d.x], 1);
        if ((unsigned)d.y < N_NODES) atomicAdd(&g_cnt[d.y], 1);
        if ((unsigned)d.z < N_NODES) atomicAdd(&g_cnt[d.z], 1);
        if ((unsigned)d.w < N_NODES) atomicAdd(&g_cnt[d.w], 1);
    }
}

__global__ __launch_bounds__(1024) void k_scan1() {
    __shared__ int warp_sums[32];
    int t = threadIdx.x, lane = t & 31, wid = t >> 5;
    int i0 = blockIdx.x * 4096 + t * 4;
    int v[4];
#pragma unroll
    for (int q = 0; q < 4; q++) {
        int i = i0 + q;
        v[q] = (i < N_NODES) ? g_cnt[i] : 0;
        if (i < N_NODES) g_dinv[i] = rsqrtf((float)v[q] + 1.0f);
    }
    int tsum = v[0] + v[1] + v[2] + v[3];
    int x = tsum;
#pragma unroll
    for (int s = 1; s < 32; s <<= 1) {
        int y = __shfl_up_sync(0xffffffffu, x, s);
        if (lane >= s) x += y;
    }
    if (lane == 31) warp_sums[wid] = x;
    __syncthreads();
    if (wid == 0) {
        int ws = warp_sums[lane];
        int xx = ws;
#pragma unroll
        for (int s = 1; s < 32; s <<= 1) {
            int y = __shfl_up_sync(0xffffffffu, xx, s);
            if (lane >= s) xx += y;
        }
        warp_sums[lane] = xx - ws;
    }
    __syncthreads();
    int run = warp_sums[wid] + (x - tsum);
#pragma unroll
    for (int q = 0; q < 4; q++) {
        int i = i0 + q;
        if (i < N_NODES) g_off[i] = run;
        run += v[q];
    }
    if (t == 1023) g_partial[blockIdx.x] = warp_sums[31] + x;
}

__global__ void k_scan3(int nblk) {
    __shared__ int sp[32];
    int t = threadIdx.x;
    if (t < 32) {
        int v = (t < nblk) ? g_partial[t] : 0;
        int x = v;
#pragma unroll
        for (int s = 1; s < 32; s <<= 1) {
            int y = __shfl_up_sync(0xffffffffu, x, s);
            if ((t & 31) >= s) x += y;
        }
        sp[t] = x - v;
    }
    __syncthreads();
    int i = blockIdx.x * blockDim.x + t;
    if (i < N_NODES) g_off[i] += sp[i >> 12];
}

// fill uses g_off as live cursors; after fill, g_off[n] = segment end.
__global__ void k_fill(const int* __restrict__ ei) {
    int e4 = (blockIdx.x * blockDim.x + threadIdx.x) * 4;
    if (e4 + 3 < N_EDGES) {
        int4 s = *(const int4*)(ei + e4);
        int4 d = *(const int4*)(ei + N_EDGES + e4);
        int ss[4] = {s.x, s.y, s.z, s.w};
        int dd[4] = {d.x, d.y, d.z, d.w};
#pragma unroll
        for (int q = 0; q < 4; q++) {
            if ((unsigned)ss[q] < N_NODES && (unsigned)dd[q] < N_NODES) {
                int pos = atomicAdd(&g_off[dd[q]], 1);
                if ((unsigned)pos < N_EDGES) g_csr_i[pos] = ss[q];
            }
        }
    }
}

// ---------------- wmma GEMM: g_h16 = fp16( dinv[row] * (A @ W16[widx]) ) ------------
#define WLD 136
#define XLD 136
__global__ __launch_bounds__(256, 2) void k_gemm_w(const float* __restrict__ xin,
                                                   int a_sel, int widx) {
    __shared__ __align__(16) __half Ws[DIM * WLD];
    __shared__ __align__(16) __half Xs[DIM * XLD];
    int tid = threadIdx.x;
    int wid = tid >> 5, lane = tid & 31;
    int wm = wid & 3;
    int wn = wid >> 2;
    int r0 = blockIdx.x * 128;

    {
        const uint4* src = (const uint4*)g_w16[widx];
#pragma unroll
        for (int it = 0; it < 8; it++) {
            int i = tid + it * 256;
            int row = i >> 4, col8 = (i & 15) << 3;
            *(uint4*)(Ws + row * WLD + col8) = src[i];
        }
    }

    if (a_sel == 0) {
        const float4* x4 = (const float4*)(xin + (size_t)r0 * DIM);
        bool full = (r0 + 128) <= N_NODES;
#pragma unroll
        for (int it = 0; it < 16; it++) {
            int j = tid + it * 256;
            int row = j >> 5, col4 = (j & 31) << 2;
            float4 v = make_float4(0.f, 0.f, 0.f, 0.f);
            if (full || (r0 + row) < N_NODES) v = x4[j];
            __half2 h0 = __floats2half2_rn(v.x, v.y);
            __half2 h1 = __floats2half2_rn(v.z, v.w);
            uint2 o;
            o.x = *(unsigned*)&h0; o.y = *(unsigned*)&h1;
            *(uint2*)(Xs + row * XLD + col4) = o;
        }
    } else {
        const uint4* src = (const uint4*)(g_h16b + (size_t)r0 * DIM);
#pragma unroll
        for (int it = 0; it < 8; it++) {
            int i = tid + it * 256;
            int row = i >> 4, col8 = (i & 15) << 3;
            *(uint4*)(Xs + row * XLD + col8) = src[i];
        }
    }
    __syncthreads();

    wmma::fragment<wmma::accumulator, 16, 16, 16, float> acc[2][4];
#pragma unroll
    for (int mi = 0; mi < 2; mi++)
#pragma unroll
        for (int ni = 0; ni < 4; ni++) wmma::fill_fragment(acc[mi][ni], 0.f);

#pragma unroll
    for (int k = 0; k < 8; k++) {
        wmma::fragment<wmma::matrix_a, 16, 16, 16, __half, wmma::row_major> af[2];
#pragma unroll
        for (int mi = 0; mi < 2; mi++)
            wmma::load_matrix_sync(af[mi], Xs + (wm * 32 + mi * 16) * XLD + k * 16, XLD);
#pragma unroll
        for (int ni = 0; ni < 4; ni++) {
            wmma::fragment<wmma::matrix_b, 16, 16, 16, __half, wmma::row_major> bf;
            wmma::load_matrix_sync(bf, Ws + (k * 16) * WLD + wn * 64 + ni * 16, WLD);
#pragma unroll
            for (int mi = 0; mi < 2; mi++)
                wmma::mma_sync(acc[mi][ni], af[mi], bf, acc[mi][ni]);
        }
    }
    __syncthreads();

    float* Cs = (float*)Ws + wid * 1024;
#pragma unroll
    for (int mi = 0; mi < 2; mi++) {
#pragma unroll
        for (int ni = 0; ni < 4; ni++)
            wmma::store_matrix_sync(Cs + ni * 16, acc[mi][ni], 64, wmma::mem_row_major);
        __syncwarp();
        int r = lane >> 1;
        int cb = (lane & 1) * 32;
        int grow = r0 + wm * 32 + mi * 16 + r;
        if (grow < N_NODES) {
            float dv = g_dinv[grow];
            const float* srcr = Cs + r * 64 + cb;
            __half* dstp = g_h16 + (size_t)grow * DIM + wn * 64 + cb;
#pragma unroll
            for (int j = 0; j < 32; j += 8) {
                float4 v0 = *(const float4*)(srcr + j);
                float4 v1 = *(const float4*)(srcr + j + 4);
                __half2 h0 = __floats2half2_rn(v0.x * dv, v0.y * dv);
                __half2 h1 = __floats2half2_rn(v0.z * dv, v0.w * dv);
                __half2 h2 = __floats2half2_rn(v1.x * dv, v1.y * dv);
                __half2 h3 = __floats2half2_rn(v1.z * dv, v1.w * dv);
                uint4 o;
                o.x = *(unsigned*)&h0; o.y = *(unsigned*)&h1;
                o.z = *(unsigned*)&h2; o.w = *(unsigned*)&h3;
                *(uint4*)(dstp + j) = o;
            }
        }
        __syncwarp();
    }
}

// ---------------- per-node gather core (all 32 lanes end with the full acc) --------
__device__ __forceinline__ void acc_row(float* acc, const uint4& r) {
    float2 f0 = __half22float2(*(__half2*)&r.x);
    float2 f1 = __half22float2(*(__half2*)&r.y);
    float2 f2 = __half22float2(*(__half2*)&r.z);
    float2 f3 = __half22float2(*(__half2*)&r.w);
    acc[0] += f0.x; acc[1] += f0.y; acc[2] += f1.x; acc[3] += f1.y;
    acc[4] += f2.x; acc[5] += f2.y; acc[6] += f3.x; acc[7] += f3.y;
}

// acc[q] (q=0..7) for dims hl*8+q, valid on ALL lanes after the shfl combine.
__device__ __forceinline__ void gather_node(const uint4* __restrict__ in4, int n,
                                            int half, int hl, float* acc) {
    float acca[8], accb[8];
    {
        uint4 sv = __ldcg(&in4[(size_t)n * 16 + hl]);
        float2 f0 = __half22float2(*(__half2*)&sv.x);
        float2 f1 = __half22float2(*(__half2*)&sv.y);
        float2 f2 = __half22float2(*(__half2*)&sv.z);
        float2 f3 = __half22float2(*(__half2*)&sv.w);
        float m = (half == 0) ? 1.f : 0.f;
        acca[0] = m * f0.x; acca[1] = m * f0.y; acca[2] = m * f1.x; acca[3] = m * f1.y;
        acca[4] = m * f2.x; acca[5] = m * f2.y; acca[6] = m * f3.x; acca[7] = m * f3.y;
#pragma unroll
        for (int q = 0; q < 8; q++) accb[q] = 0.f;
    }
    int end = g_off[n];
    int j = end - g_cnt[n];
    for (; j + 16 <= end; j += 16) {
        int s0 = __ldcs(&g_csr_i[j + half]);
        int s1 = __ldcs(&g_csr_i[j + 2 + half]);
        int s2 = __ldcs(&g_csr_i[j + 4 + half]);
        int s3 = __ldcs(&g_csr_i[j + 6 + half]);
        int s4 = __ldcs(&g_csr_i[j + 8 + half]);
        int s5 = __ldcs(&g_csr_i[j + 10 + half]);
        int s6 = __ldcs(&g_csr_i[j + 12 + half]);
        int s7 = __ldcs(&g_csr_i[j + 14 + half]);
        uint4 r0 = __ldcg(&in4[(size_t)s0 * 16 + hl]);
        uint4 r1 = __ldcg(&in4[(size_t)s1 * 16 + hl]);
        uint4 r2 = __ldcg(&in4[(size_t)s2 * 16 + hl]);
        uint4 r3 = __ldcg(&in4[(size_t)s3 * 16 + hl]);
        uint4 r4 = __ldcg(&in4[(size_t)s4 * 16 + hl]);
        uint4 r5 = __ldcg(&in4[(size_t)s5 * 16 + hl]);
        uint4 r6 = __ldcg(&in4[(size_t)s6 * 16 + hl]);
        uint4 r7 = __ldcg(&in4[(size_t)s7 * 16 + hl]);
        acc_row(acca, r0); acc_row(accb, r1);
        acc_row(acca, r2); acc_row(accb, r3);
        acc_row(acca, r4); acc_row(accb, r5);
        acc_row(acca, r6); acc_row(accb, r7);
    }
    for (; j + 4 <= end; j += 4) {
        int s0 = __ldcs(&g_csr_i[j + half]);
        int s1 = __ldcs(&g_csr_i[j + 2 + half]);
        uint4 r0 = __ldcg(&in4[(size_t)s0 * 16 + hl]);
        uint4 r1 = __ldcg(&in4[(size_t)s1 * 16 + hl]);
        acc_row(acca, r0); acc_row(accb, r1);
    }
    for (; j + 2 <= end; j += 2) {
        int s = __ldcs(&g_csr_i[j + half]);
        uint4 r = __ldcg(&in4[(size_t)s * 16 + hl]);
        acc_row(acca, r);
    }
    if (j + half < end) {
        int s = __ldcs(&g_csr_i[j + half]);
        uint4 r = __ldcg(&in4[(size_t)s * 16 + hl]);
        acc_row(accb, r);
    }
#pragma unroll
    for (int q = 0; q < 8; q++) {
        float v = acca[q] + accb[q];
        acc[q] = v + __shfl_xor_sync(0xffffffffu, v, 16);
    }
}

// ---------------- agg (layers 1 & 2): fp16 out with fused bias/relu/scale ----------
__global__ __launch_bounds__(256) void k_agg(int in_sel, int out_scale,
                                             const float* __restrict__ bias) {
    int n = (blockIdx.x * blockDim.x + threadIdx.x) >> 5;
    int lane = threadIdx.x & 31;
    if (n >= N_NODES) return;
    int half = lane >> 4, hl = lane & 15;
    const uint4* in4 = (const uint4*)(in_sel ? g_h16b : g_h16);
    float dn = g_dinv[n];

    float acc[8];
    gather_node(in4, n, half, hl, acc);

    if (half == 0) {
#pragma unroll
        for (int q = 0; q < 8; q++) acc[q] *= dn;
        float4 b0 = *(const float4*)(bias + hl * 8);
        float4 b1 = *(const float4*)(bias + hl * 8 + 4);
        acc[0] = fmaxf(acc[0] + b0.x, 0.f); acc[1] = fmaxf(acc[1] + b0.y, 0.f);
        acc[2] = fmaxf(acc[2] + b0.z, 0.f); acc[3] = fmaxf(acc[3] + b0.w, 0.f);
        acc[4] = fmaxf(acc[4] + b1.x, 0.f); acc[5] = fmaxf(acc[5] + b1.y, 0.f);
        acc[6] = fmaxf(acc[6] + b1.z, 0.f); acc[7] = fmaxf(acc[7] + b1.w, 0.f);
        if (out_scale) {
#pragma unroll
            for (int q = 0; q < 8; q++) acc[q] *= dn;
        }
        __half2 h0 = __floats2half2_rn(acc[0], acc[1]);
        __half2 h1 = __floats2half2_rn(acc[2], acc[3]);
        __half2 h2 = __floats2half2_rn(acc[4], acc[5]);
        __half2 h3 = __floats2half2_rn(acc[6], acc[7]);
        uint4 o;
        o.x = *(unsigned*)&h0; o.y = *(unsigned*)&h1;
        o.z = *(unsigned*)&h2; o.w = *(unsigned*)&h3;
        *(uint4*)(g_h16b + (size_t)n * DIM + hl * 8) = o;
    }
}

// ---------------- agg3 + readout fused: warp = 8 consecutive nodes -----------------
// gathers from g_h16b (scaled), accumulates dn*acc runs per graph, flushes atomically.
#define POOL_NPW 8
__global__ __launch_bounds__(256) void k_agg_pool(const int* __restrict__ batch) {
    int warp = (blockIdx.x * blockDim.x + threadIdx.x) >> 5;
    int lane = threadIdx.x & 31;
    int half = lane >> 4, hl = lane & 15;
    int nbase = warp * POOL_NPW;
    if (nbase >= N_NODES) return;
    const uint4* in4 = (const uint4*)g_h16b;

    float racc[8];
#pragma unroll
    for (int q = 0; q < 8; q++) racc[q] = 0.f;
    int gprev = -1, rcnt = 0;

    for (int i = 0; i < POOL_NPW; i++) {
        int n = nbase + i;
        if (n >= N_NODES) break;
        int b = batch[n];
        if ((unsigned)b >= N_GRAPHS) b = 0;
        if (b != gprev) {
            if (gprev >= 0) {
                int d = hl * 8 + half * 4;
#pragma unroll
                for (int q = 0; q < 4; q++)
                    atomicAdd(&g_gsum[gprev * DIM + d + q], racc[half * 4 + q]);
                if (lane == 0) atomicAdd(&g_gcnt[gprev], (float)rcnt);
            }
#pragma unroll
            for (int q = 0; q < 8; q++) racc[q] = 0.f;
            rcnt = 0;
            gprev = b;
        }
        float acc[8];
        gather_node(in4, n, half, hl, acc);
        float dn = g_dinv[n];
#pragma unroll
        for (int q = 0; q < 8; q++) racc[q] += dn * acc[q];
        rcnt++;
    }
    if (gprev >= 0) {
        int d = hl * 8 + half * 4;
#pragma unroll
        for (int q = 0; q < 4; q++)
            atomicAdd(&g_gsum[gprev * DIM + d + q], racc[half * 4 + q]);
        if (lane == 0) atomicAdd(&g_gcnt[gprev], (float)rcnt);
    }
}

// ---------------- final ----------------
__global__ __launch_bounds__(128) void k_final(const float* __restrict__ W3,
                                               const float* __restrict__ b3,
                                               float* __restrict__ out) {
    __shared__ float m[DIM];
    int g = blockIdx.x;
    int d = threadIdx.x;
    float c = g_gcnt[g];
    float inv = (c > 0.f) ? (1.f / c) : 0.f;
    m[d] = g_gsum[g * DIM + d] * inv;
    __syncthreads();
    float acc = 0.f;
#pragma unroll 8
    for (int k = 0; k < DIM; k++)
        acc = fmaf(m[k], W3[k * DIM + d], acc);
    out[g * DIM + d] = (c > 0.f) ? (acc + b3[d]) : 0.f;
}

// ---------------- launch: fork gemm1 onto a side stream -----------------
extern "C" void kernel_launch(void* const* d_in, const int* in_sizes, int n_in,
                              void* d_out, int out_size) {
    (void)in_sizes; (void)n_in; (void)out_size;
    const float* x     = (const float*)d_in[0];
    const int*   ei    = (const int*)d_in[1];
    const int*   batch = (const int*)d_in[2];
    const float* W1    = (const float*)d_in[3];
    const float* b1    = (const float*)d_in[4];
    const float* W2    = (const float*)d_in[5];
    const float* b2    = (const float*)d_in[6];
    const float* W3    = (const float*)d_in[7];
    const float* b3    = (const float*)d_in[8];
    float* out = (float*)d_out;

    int scan_blocks = (N_NODES + 4095) / 4096;
    int gemm_blocks = (N_NODES + 127) / 128;
    int agg_blocks = (N_NODES * 32 + 255) / 256;
    int pool_blocks = (N_NODES + 8 * POOL_NPW - 1) / (8 * POOL_NPW);

    cudaStream_t s2;
    cudaStreamCreateWithFlags(&s2, cudaStreamNonBlocking);
    cudaEvent_t ev_fork, ev_dinv, ev_gemm1;
    cudaEventCreateWithFlags(&ev_fork, cudaEventDisableTiming);
    cudaEventCreateWithFlags(&ev_dinv, cudaEventDisableTiming);
    cudaEventCreateWithFlags(&ev_gemm1, cudaEventDisableTiming);

    // fork: prepw runs on s2 concurrently with zero/degree
    cudaEventRecord(ev_fork, 0);
    cudaStreamWaitEvent(s2, ev_fork, 0);
    k_prepw<<<16, 256, 0, s2>>>(W1, W2);

    // main: CSR setup chain
    k_zero<<<(N_NODES + 255) / 256, 256>>>();
    k_degree<<<(N_EDGES / 4 + 255) / 256, 256>>>(ei);
    k_scan1<<<scan_blocks, 1024>>>();
    cudaEventRecord(ev_dinv, 0);

    // s2: gemm1 (needs prepw + dinv)
    cudaStreamWaitEvent(s2, ev_dinv, 0);
    k_gemm_w<<<gemm_blocks, 256, 0, s2>>>(x, 0, 0);
    cudaEventRecord(ev_gemm1, s2);

    // main continues CSR build concurrently with gemm1
    k_scan3<<<(N_NODES + 255) / 256, 256>>>(scan_blocks);
    k_fill<<<(N_EDGES / 4 + 255) / 256, 256>>>(ei);

    // join: agg1 needs gemm1 (g_h16) + fill (CSR)
    cudaStreamWaitEvent(0, ev_gemm1, 0);

    // layer 1: agg(g_h16) -> g_h16b = relu(dn*acc + b1)
    k_agg<<<agg_blocks, 256>>>(0, 0, b1);
    // layer 2: gemm2 -> g_h16 (scaled) ; agg -> g_h16b = relu(dn*acc + b2) * dn
    k_gemm_w<<<gemm_blocks, 256>>>(x, 1, 1);
    k_agg<<<agg_blocks, 256>>>(0, 1, b2);
    // layer 3 + readout fused: pooled segmented sums into g_gsum/g_gcnt
    k_agg_pool<<<pool_blocks, 256>>>(batch);

    k_final<<<N_GRAPHS, 128>>>(W3, b3, out);
}